// round 4
// baseline (speedup 1.0000x reference)
#include <cuda_runtime.h>
#include <math.h>

#define NTOK 80000
#define KK   4
#define ROWS 16
#define NTHR 512

// ---------------- smem layout (float offsets) ----------------
constexpr int OFF_WM1  = 0;                  // 384*64 = 24576
constexpr int OFF_WTP0 = OFF_WM1  + 24576;   // 4096
constexpr int OFF_SCUR = OFF_WTP0 + 4096;    // 16*256 = 4096
constexpr int OFF_VCUR = OFF_SCUR + 4096;    // 16*384 = 6144
constexpr int OFF_XS   = OFF_VCUR + 6144;    // transposed x, stride 20: 192*20 = 3840
constexpr int OFF_TMP  = OFF_XS   + 3840;    // transposed [s_k|n_k|p0], stride 20: 161*20 -> 3232
constexpr int OFF_VKA  = OFF_TMP  + 3232;    // 16*192
constexpr int OFF_VKB  = OFF_VKA  + 3072;    // 16*192
constexpr int OFF_MBUF = OFF_VKB  + 3072;    // 16*128 = 2048
constexpr int OFF_GB   = OFF_MBUF + 2048;    // gamma 384 + beta 384
constexpr int OFF_BM1  = OFF_GB   + 768;     // 64
constexpr int OFF_WM2  = OFF_BM1  + 64;      // 64
constexpr int OFF_SP1  = OFF_WM2  + 64;      // 16*4
constexpr int OFF_EV   = OFF_SP1  + 64;      // 16*4
constexpr int SMEM_FLOATS = OFF_EV + 64;     // 55200 floats
constexpr int SMEM_BYTES  = SMEM_FLOATS * 4; // 220800 B
// hbuf (normalized layernorm output, 16*384) overlays freed XS+TMP regions
constexpr int OFF_HBUF = OFF_XS;             // needs 6144 <= 3840+3232 = 7072  OK

// ---------------- global scratch (no allocs allowed) ----------------
__device__ float g_SV[(size_t)NTOK * 2560];  // [row][k][640] : S(256) then V(384)
__device__ float g_alpha[(size_t)NTOK * KK];

__global__ void __launch_bounds__(NTHR, 1)
fuse_k1(const float* __restrict__ x0, const float* __restrict__ x1,
        const float* __restrict__ x2, const float* __restrict__ x3,
        const float* __restrict__ W_l0, const float* __restrict__ W_l1,
        const float* __restrict__ W_l2, const float* __restrict__ W_tp0,
        const float* __restrict__ W_tp1, const float* __restrict__ Ws,
        const float* __restrict__ bs, const float* __restrict__ Wv1o,
        const float* __restrict__ Wv1e, const float* __restrict__ gamma,
        const float* __restrict__ beta, const float* __restrict__ Wm1,
        const float* __restrict__ bm1, const float* __restrict__ Wm2,
        const float* __restrict__ bm2)
{
    extern __shared__ float sm[];
    const int t  = threadIdx.x;
    const int r0 = blockIdx.x * ROWS;

    // stage block-resident weights
    for (int i = t; i < 384*64; i += NTHR) sm[OFF_WM1 + i] = Wm1[i];
    for (int i = t; i < 64*64;  i += NTHR) sm[OFF_WTP0 + i] = W_tp0[i];
    for (int i = t; i < 384;    i += NTHR) { sm[OFF_GB + i] = gamma[i]; sm[OFF_GB + 384 + i] = beta[i]; }
    if (t < 64) { sm[OFF_BM1 + t] = bm1[t]; sm[OFF_WM2 + t] = Wm2[t]; }
    __syncthreads();

    const float* xs_ptr[KK] = {x0, x1, x2, x3};
    float* vkbuf = sm + OFF_VKA;
    float* vpbuf = sm + OFF_VKB;

    for (int k = 0; k < KK; ++k) {
        const float* xg = xs_ptr[k];

        // ---- stage x_s (transposed, stride 20) ----
        for (int idx = t; idx < ROWS*128; idx += NTHR) {
            int r = idx >> 7, c = idx & 127;
            sm[OFF_XS + c*20 + r] = xg[(size_t)(r0 + r)*480 + c];
        }
        __syncthreads();

        // ---- op1: s_k[j] = inv0 * sum_i x_s[i] W_l0[k][i][j] ----
        {
            int j = t & 127, rq = t >> 7;            // rq: 4 groups of 4 rows
            float a0 = 0, a1 = 0, a2 = 0, a3 = 0;
            const float* W = W_l0 + k*128*128;
            #pragma unroll 4
            for (int i = 0; i < 128; ++i) {
                float w = W[i*128 + j];
                const float4 xv = *reinterpret_cast<const float4*>(&sm[OFF_XS + i*20 + rq*4]);
                a0 += xv.x*w; a1 += xv.y*w; a2 += xv.z*w; a3 += xv.w*w;
            }
            const float s = 0.08838834764831845f;    // 1/sqrt(128)
            sm[OFF_TMP + j*20 + rq*4 + 0] = a0*s;
            sm[OFF_TMP + j*20 + rq*4 + 1] = a1*s;
            sm[OFF_TMP + j*20 + rq*4 + 2] = a2*s;
            sm[OFF_TMP + j*20 + rq*4 + 3] = a3*s;
        }
        __syncthreads();

        // ---- stage x_v (192 cols) ----
        for (int idx = t; idx < ROWS*192; idx += NTHR) {
            int r = idx / 192, c = idx % 192;
            sm[OFF_XS + c*20 + r] = xg[(size_t)(r0 + r)*480 + 128 + c];
        }
        __syncthreads();

        // ---- op2: v_k[j][m] = inv1 * sum_i x_v[i][m] W_l1[k][i][j] ----
        {
            int j = t & 63, rg = t >> 6;             // rg: 8 groups of 2 rows
            float a[2][3] = {};
            const float* W = W_l1 + k*64*64;
            #pragma unroll 2
            for (int i = 0; i < 64; ++i) {
                float w = W[i*64 + j];
                #pragma unroll
                for (int m = 0; m < 3; ++m) {
                    float2 xv = *reinterpret_cast<const float2*>(&sm[OFF_XS + (i*3 + m)*20 + rg*2]);
                    a[0][m] += xv.x*w; a[1][m] += xv.y*w;
                }
            }
            #pragma unroll
            for (int rr = 0; rr < 2; ++rr)
                #pragma unroll
                for (int m = 0; m < 3; ++m)
                    vkbuf[(rg*2 + rr)*192 + j*3 + m] = a[rr][m]*0.125f;
        }
        __syncthreads();

        // ---- stage x_T (160 cols) ----
        for (int idx = t; idx < ROWS*160; idx += NTHR) {
            int r = idx / 160, c = idx % 160;
            sm[OFF_XS + c*20 + r] = xg[(size_t)(r0 + r)*480 + 320 + c];
        }
        __syncthreads();

        // ---- op3: n_k[j] = inv2 * || sum_i x_T[i][:] W_l2[k][i][j] || ----
        {
            int j = t & 31, r = t >> 5;              // 1 row per thread
            float a[5] = {};
            const float* W = W_l2 + k*32*32;
            #pragma unroll 2
            for (int i = 0; i < 32; ++i) {
                float w = W[i*32 + j];
                #pragma unroll
                for (int m = 0; m < 5; ++m) a[m] += sm[OFF_XS + (i*5 + m)*20 + r]*w;
            }
            float s2 = a[0]*a[0] + a[1]*a[1] + a[2]*a[2] + a[3]*a[3] + a[4]*a[4];
            sm[OFF_TMP + (128 + j)*20 + r] = sqrtf(s2)*0.17677669529663687f;  // 1/sqrt(32)
        }

        // ---- op4: p0, p1 (warp per row) ----
        {
            int r = t >> 5, lane = t & 31;
            float p0 = 0, px = 0, py = 0, pz = 0;
            if (k > 0) {
                #pragma unroll
                for (int jj = 0; jj < 2; ++jj) {
                    int j = lane + jj*32;
                    float u0x=0,u0y=0,u0z=0,u1x=0,u1y=0,u1z=0;
                    for (int i = 0; i < 64; ++i) {
                        float va = vkbuf[r*192 + i*3 + 0];
                        float vb = vkbuf[r*192 + i*3 + 1];
                        float vc = vkbuf[r*192 + i*3 + 2];
                        float w0 = sm[OFF_WTP0 + i*64 + j];
                        float w1 = __ldg(&W_tp1[i*64 + j]);
                        u0x += va*w0; u0y += vb*w0; u0z += vc*w0;
                        u1x += va*w1; u1y += vb*w1; u1z += vc*w1;
                    }
                    float vx = vpbuf[r*192 + j*3 + 0];
                    float vy = vpbuf[r*192 + j*3 + 1];
                    float vz = vpbuf[r*192 + j*3 + 2];
                    p0 += u0x*vx + u0y*vy + u0z*vz;
                    px += u1y*vz - u1z*vy;
                    py += u1z*vx - u1x*vz;
                    pz += u1x*vy - u1y*vx;
                }
            }
            #pragma unroll
            for (int off = 16; off > 0; off >>= 1) {
                p0 += __shfl_down_sync(0xffffffffu, p0, off);
                px += __shfl_down_sync(0xffffffffu, px, off);
                py += __shfl_down_sync(0xffffffffu, py, off);
                pz += __shfl_down_sync(0xffffffffu, pz, off);
            }
            if (lane == 0) {
                sm[OFF_TMP + 160*20 + r] = p0*0.009021097956087905f;   // 1/(sqrt(3)*64)
                sm[OFF_SP1 + r*4 + 0] = px*0.011048543456039806f;      // 1/(sqrt(2)*64)
                sm[OFF_SP1 + r*4 + 1] = py*0.011048543456039806f;
                sm[OFF_SP1 + r*4 + 2] = pz*0.011048543456039806f;
            }
        }
        __syncthreads();

        // ---- op5: s_tilde = [s_k|n_k|p0](161) @ Ws[k] + bs[k] ----
        {
            int c = t & 255, h = t >> 8;             // h: 2 groups of 8 rows
            float acc[8] = {};
            const float* W = Ws + k*161*256;
            for (int i = 0; i < 161; ++i) {
                float w = W[i*256 + c];
                const float4 t0 = *reinterpret_cast<const float4*>(&sm[OFF_TMP + i*20 + h*8]);
                const float4 t1 = *reinterpret_cast<const float4*>(&sm[OFF_TMP + i*20 + h*8 + 4]);
                acc[0] += t0.x*w; acc[1] += t0.y*w; acc[2] += t0.z*w; acc[3] += t0.w*w;
                acc[4] += t1.x*w; acc[5] += t1.y*w; acc[6] += t1.z*w; acc[7] += t1.w*w;
            }
            float bb = bs[k*256 + c];
            #pragma unroll
            for (int rr = 0; rr < 8; ++rr)
                sm[OFF_SCUR + (h*8 + rr)*256 + c] = acc[rr] + bb;
        }

        // ---- op6: v1o, v1e -> Vcur ----
        {
            int j = t & 63, rg = t >> 6;
            float a[2][3] = {};
            const float* W = Wv1o + k*64*64;
            #pragma unroll 2
            for (int i = 0; i < 64; ++i) {
                float w = W[i*64 + j];
                #pragma unroll
                for (int m = 0; m < 3; ++m) {
                    a[0][m] += vkbuf[(rg*2    )*192 + i*3 + m]*w;
                    a[1][m] += vkbuf[(rg*2 + 1)*192 + i*3 + m]*w;
                }
            }
            float we = __ldg(&Wv1e[k*64 + j]);
            #pragma unroll
            for (int rr = 0; rr < 2; ++rr) {
                int r = rg*2 + rr;
                #pragma unroll
                for (int m = 0; m < 3; ++m) {
                    sm[OFF_VCUR + r*384 + j*3 + m]       = a[rr][m]*0.125f;
                    sm[OFF_VCUR + r*384 + 192 + j*3 + m] = sm[OFF_SP1 + r*4 + m]*we;
                }
            }
        }
        __syncthreads();

        // ---- m: norms of V triples ----
        for (int idx = t; idx < ROWS*128; idx += NTHR) {
            int r = idx >> 7, c = idx & 127;
            float a = sm[OFF_VCUR + r*384 + c*3];
            float b = sm[OFF_VCUR + r*384 + c*3 + 1];
            float d = sm[OFF_VCUR + r*384 + c*3 + 2];
            sm[OFF_MBUF + r*128 + c] = sqrtf(a*a + b*b + d*d);
        }
        __syncthreads();

        // ---- layernorm + MLP + e_k (warp per row) ----
        {
            int r = t >> 5, lane = t & 31;
            float s = 0.f, s2 = 0.f;
            #pragma unroll
            for (int c = lane; c < 384; c += 32) {
                float v = (c < 256) ? sm[OFF_SCUR + r*256 + c] : sm[OFF_MBUF + r*128 + c - 256];
                s += v; s2 += v*v;
            }
            #pragma unroll
            for (int off = 16; off > 0; off >>= 1) {
                s  += __shfl_xor_sync(0xffffffffu, s,  off);
                s2 += __shfl_xor_sync(0xffffffffu, s2, off);
            }
            float mu   = s  * (1.f/384.f);
            float var  = s2 * (1.f/384.f) - mu*mu;
            float rstd = rsqrtf(var + 1e-5f);
            #pragma unroll
            for (int c = lane; c < 384; c += 32) {
                float v = (c < 256) ? sm[OFF_SCUR + r*256 + c] : sm[OFF_MBUF + r*128 + c - 256];
                sm[OFF_HBUF + r*384 + c] = (v - mu)*rstd*sm[OFF_GB + c] + sm[OFF_GB + 384 + c];
            }
            __syncwarp();
            float a0 = 0.f, a1 = 0.f;
            #pragma unroll 4
            for (int i = 0; i < 384; ++i) {
                float hh = sm[OFF_HBUF + r*384 + i];
                a0 += hh * sm[OFF_WM1 + i*64 + lane];
                a1 += hh * sm[OFF_WM1 + i*64 + lane + 32];
            }
            a0 += sm[OFF_BM1 + lane]; a1 += sm[OFF_BM1 + lane + 32];
            float e = a0/(1.f + expf(-a0)) * sm[OFF_WM2 + lane]
                    + a1/(1.f + expf(-a1)) * sm[OFF_WM2 + lane + 32];
            #pragma unroll
            for (int off = 16; off > 0; off >>= 1)
                e += __shfl_down_sync(0xffffffffu, e, off);
            if (lane == 0) sm[OFF_EV + r*4 + k] = e + __ldg(&bm2[0]);
        }

        // ---- spill S,V for this k ----
        for (int idx = t; idx < ROWS*640; idx += NTHR) {
            int r = idx / 640, c = idx % 640;
            float v = (c < 256) ? sm[OFF_SCUR + r*256 + c] : sm[OFF_VCUR + r*384 + c - 256];
            g_SV[(size_t)(r0 + r)*2560 + (size_t)k*640 + c] = v;
        }

        { float* tp = vkbuf; vkbuf = vpbuf; vpbuf = tp; }
        __syncthreads();
    }

    // ---- softmax over K ----
    if (t < ROWS) {
        float e0 = sm[OFF_EV + t*4 + 0], e1 = sm[OFF_EV + t*4 + 1];
        float e2 = sm[OFF_EV + t*4 + 2], e3 = sm[OFF_EV + t*4 + 3];
        float mx = fmaxf(fmaxf(e0, e1), fmaxf(e2, e3));
        float z0 = expf(e0 - mx), z1 = expf(e1 - mx), z2 = expf(e2 - mx), z3 = expf(e3 - mx);
        float inv = 1.f/(z0 + z1 + z2 + z3);
        g_alpha[(size_t)(r0 + t)*4 + 0] = z0*inv;
        g_alpha[(size_t)(r0 + t)*4 + 1] = z1*inv;
        g_alpha[(size_t)(r0 + t)*4 + 2] = z2*inv;
        g_alpha[(size_t)(r0 + t)*4 + 3] = z3*inv;
    }
}

// out = concat(flatten((alpha*S).sum(k)), flatten((alpha*V).sum(k)))
__global__ void fuse_k2(float* __restrict__ out)
{
    int r = blockIdx.x;
    int c = threadIdx.x;  // 640
    __shared__ float al[4];
    if (c < 4) al[c] = g_alpha[(size_t)r*4 + c];
    __syncthreads();
    const float* sv = g_SV + (size_t)r*2560;
    float acc = al[0]*sv[c] + al[1]*sv[640 + c] + al[2]*sv[1280 + c] + al[3]*sv[1920 + c];
    if (c < 256) out[(size_t)r*256 + c] = acc;
    else         out[(size_t)NTOK*256 + (size_t)r*384 + (c - 256)] = acc;
}

extern "C" void kernel_launch(void* const* d_in, const int* in_sizes, int n_in,
                              void* d_out, int out_size)
{
    (void)in_sizes; (void)n_in; (void)out_size;
    cudaFuncSetAttribute(fuse_k1, cudaFuncAttributeMaxDynamicSharedMemorySize, SMEM_BYTES);

    fuse_k1<<<NTOK/ROWS, NTHR, SMEM_BYTES>>>(
        (const float*)d_in[0],  (const float*)d_in[1],  (const float*)d_in[2],
        (const float*)d_in[3],  (const float*)d_in[4],  (const float*)d_in[5],
        (const float*)d_in[6],  (const float*)d_in[7],  (const float*)d_in[8],
        (const float*)d_in[9],  (const float*)d_in[10], (const float*)d_in[11],
        (const float*)d_in[12], (const float*)d_in[13], (const float*)d_in[14],
        (const float*)d_in[15], (const float*)d_in[16], (const float*)d_in[17],
        (const float*)d_in[18]);

    fuse_k2<<<NTOK, 640>>>((float*)d_out);
}

// round 5
// speedup vs baseline: 1.2616x; 1.2616x over previous
#include <cuda_runtime.h>
#include <math.h>

#define NTOK 80000
#define KK   4
#define ROWS 16
#define NTHR 512

// ---------------- smem layout (float offsets), 106 KB -> 2 CTAs/SM ----------------
constexpr int OFF_SCUR = 0;                  // 16*256 = 4096
constexpr int OFF_VCUR = OFF_SCUR + 4096;    // 16*384 = 6144
constexpr int OFF_XS   = OFF_VCUR + 6144;    // transposed x, stride 20: 192*20 = 3840
constexpr int OFF_TMP  = OFF_XS   + 3840;    // transposed [s_k|n_k|p0], stride 20: 161*20 -> 3232
constexpr int OFF_VKA  = OFF_TMP  + 3232;    // 16*192 = 3072
constexpr int OFF_VKB  = OFF_VKA  + 3072;    // 16*192 = 3072
constexpr int OFF_MBUF = OFF_VKB  + 3072;    // 16*128 = 2048
constexpr int OFF_GB   = OFF_MBUF + 2048;    // gamma 384 + beta 384
constexpr int OFF_BM1  = OFF_GB   + 768;     // 64
constexpr int OFF_WM2  = OFF_BM1  + 64;      // 64
constexpr int OFF_SP1  = OFF_WM2  + 64;      // 16*4
constexpr int OFF_EV   = OFF_SP1  + 64;      // 16*4
constexpr int SMEM_FLOATS = OFF_EV + 64;     // 26528 floats
constexpr int SMEM_BYTES  = SMEM_FLOATS * 4; // 106112 B -> 2 blocks/SM
// hbuf (normalized layernorm output, 16*384=6144) overlays freed XS+TMP (7072)
constexpr int OFF_HBUF = OFF_XS;

// ---------------- global scratch (no allocs allowed) ----------------
__device__ float g_SV[(size_t)NTOK * 2560];  // [row][k][640] : S(256) then V(384)
__device__ float g_alpha[(size_t)NTOK * KK];

__global__ void __launch_bounds__(NTHR, 2)
fuse_k1(const float* __restrict__ x0, const float* __restrict__ x1,
        const float* __restrict__ x2, const float* __restrict__ x3,
        const float* __restrict__ W_l0, const float* __restrict__ W_l1,
        const float* __restrict__ W_l2, const float* __restrict__ W_tp0,
        const float* __restrict__ W_tp1, const float* __restrict__ Ws,
        const float* __restrict__ bs, const float* __restrict__ Wv1o,
        const float* __restrict__ Wv1e, const float* __restrict__ gamma,
        const float* __restrict__ beta, const float* __restrict__ Wm1,
        const float* __restrict__ bm1, const float* __restrict__ Wm2,
        const float* __restrict__ bm2)
{
    extern __shared__ float sm[];
    const int t  = threadIdx.x;
    const int r0 = blockIdx.x * ROWS;

    // stage small block-resident constants
    for (int i = t; i < 384; i += NTHR) { sm[OFF_GB + i] = gamma[i]; sm[OFF_GB + 384 + i] = beta[i]; }
    if (t < 64) { sm[OFF_BM1 + t] = bm1[t]; sm[OFF_WM2 + t] = Wm2[t]; }
    __syncthreads();

    const float* xs_ptr[KK] = {x0, x1, x2, x3};
    float* vkbuf = sm + OFF_VKA;
    float* vpbuf = sm + OFF_VKB;

    for (int k = 0; k < KK; ++k) {
        const float* xg = xs_ptr[k];

        // ---- stage x_s (transposed, stride 20) ----
        for (int idx = t; idx < ROWS*128; idx += NTHR) {
            int r = idx >> 7, c = idx & 127;
            sm[OFF_XS + c*20 + r] = xg[(size_t)(r0 + r)*480 + c];
        }
        __syncthreads();

        // ---- op1: s_k[j] = inv0 * sum_i x_s[i] W_l0[k][i][j] ----
        {
            int j = t & 127, rq = t >> 7;            // 4 groups of 4 rows
            float a0 = 0, a1 = 0, a2 = 0, a3 = 0;
            const float* W = W_l0 + k*128*128;
            #pragma unroll 4
            for (int i = 0; i < 128; ++i) {
                float w = __ldg(&W[i*128 + j]);
                const float4 xv = *reinterpret_cast<const float4*>(&sm[OFF_XS + i*20 + rq*4]);
                a0 += xv.x*w; a1 += xv.y*w; a2 += xv.z*w; a3 += xv.w*w;
            }
            const float s = 0.08838834764831845f;    // 1/sqrt(128)
            sm[OFF_TMP + j*20 + rq*4 + 0] = a0*s;
            sm[OFF_TMP + j*20 + rq*4 + 1] = a1*s;
            sm[OFF_TMP + j*20 + rq*4 + 2] = a2*s;
            sm[OFF_TMP + j*20 + rq*4 + 3] = a3*s;
        }
        __syncthreads();

        // ---- stage x_v (192 cols) ----
        for (int idx = t; idx < ROWS*192; idx += NTHR) {
            int r = idx / 192, c = idx % 192;
            sm[OFF_XS + c*20 + r] = xg[(size_t)(r0 + r)*480 + 128 + c];
        }
        __syncthreads();

        // ---- op2: v_k[j][m] = inv1 * sum_i x_v[i][m] W_l1[k][i][j] ----
        {
            int j = t & 63, rg = t >> 6;             // 8 groups of 2 rows
            float a[2][3] = {};
            const float* W = W_l1 + k*64*64;
            #pragma unroll 4
            for (int i = 0; i < 64; ++i) {
                float w = __ldg(&W[i*64 + j]);
                #pragma unroll
                for (int m = 0; m < 3; ++m) {
                    float2 xv = *reinterpret_cast<const float2*>(&sm[OFF_XS + (i*3 + m)*20 + rg*2]);
                    a[0][m] += xv.x*w; a[1][m] += xv.y*w;
                }
            }
            #pragma unroll
            for (int rr = 0; rr < 2; ++rr)
                #pragma unroll
                for (int m = 0; m < 3; ++m)
                    vkbuf[(rg*2 + rr)*192 + j*3 + m] = a[rr][m]*0.125f;
        }
        __syncthreads();

        // ---- stage x_T (160 cols) ----
        for (int idx = t; idx < ROWS*160; idx += NTHR) {
            int r = idx / 160, c = idx % 160;
            sm[OFF_XS + c*20 + r] = xg[(size_t)(r0 + r)*480 + 320 + c];
        }
        __syncthreads();

        // ---- phase: op4 on warps 0-7 (2 rows/warp), op3 on warps 8-15 ----
        {
            int w = t >> 5, lane = t & 31;
            if (w < 8) {
                // op4: p0/p1 for rows (2w, 2w+1)
                int ra = 2*w, rb = 2*w + 1;
                float p0a=0,pxa=0,pya=0,pza=0, p0b=0,pxb=0,pyb=0,pzb=0;
                if (k > 0) {
                    #pragma unroll
                    for (int jj = 0; jj < 2; ++jj) {
                        int j = jj*32 + lane;
                        float u0a0=0,u0a1=0,u0a2=0,u1a0=0,u1a1=0,u1a2=0;
                        float u0b0=0,u0b1=0,u0b2=0,u1b0=0,u1b1=0,u1b2=0;
                        #pragma unroll 2
                        for (int i = 0; i < 64; ++i) {
                            float w0 = __ldg(&W_tp0[i*64 + j]);
                            float w1 = __ldg(&W_tp1[i*64 + j]);
                            float vaa = vkbuf[ra*192 + i*3 + 0];
                            float vab = vkbuf[ra*192 + i*3 + 1];
                            float vac = vkbuf[ra*192 + i*3 + 2];
                            float vba = vkbuf[rb*192 + i*3 + 0];
                            float vbb = vkbuf[rb*192 + i*3 + 1];
                            float vbc = vkbuf[rb*192 + i*3 + 2];
                            u0a0 += vaa*w0; u0a1 += vab*w0; u0a2 += vac*w0;
                            u1a0 += vaa*w1; u1a1 += vab*w1; u1a2 += vac*w1;
                            u0b0 += vba*w0; u0b1 += vbb*w0; u0b2 += vbc*w0;
                            u1b0 += vba*w1; u1b1 += vbb*w1; u1b2 += vbc*w1;
                        }
                        float vx = vpbuf[ra*192 + j*3 + 0];
                        float vy = vpbuf[ra*192 + j*3 + 1];
                        float vz = vpbuf[ra*192 + j*3 + 2];
                        p0a += u0a0*vx + u0a1*vy + u0a2*vz;
                        pxa += u1a1*vz - u1a2*vy;
                        pya += u1a2*vx - u1a0*vz;
                        pza += u1a0*vy - u1a1*vx;
                        vx = vpbuf[rb*192 + j*3 + 0];
                        vy = vpbuf[rb*192 + j*3 + 1];
                        vz = vpbuf[rb*192 + j*3 + 2];
                        p0b += u0b0*vx + u0b1*vy + u0b2*vz;
                        pxb += u1b1*vz - u1b2*vy;
                        pyb += u1b2*vx - u1b0*vz;
                        pzb += u1b0*vy - u1b1*vx;
                    }
                }
                #pragma unroll
                for (int off = 16; off > 0; off >>= 1) {
                    p0a += __shfl_down_sync(0xffffffffu, p0a, off);
                    pxa += __shfl_down_sync(0xffffffffu, pxa, off);
                    pya += __shfl_down_sync(0xffffffffu, pya, off);
                    pza += __shfl_down_sync(0xffffffffu, pza, off);
                    p0b += __shfl_down_sync(0xffffffffu, p0b, off);
                    pxb += __shfl_down_sync(0xffffffffu, pxb, off);
                    pyb += __shfl_down_sync(0xffffffffu, pyb, off);
                    pzb += __shfl_down_sync(0xffffffffu, pzb, off);
                }
                if (lane == 0) {
                    const float c0 = 0.009021097956087905f;   // 1/(sqrt(3)*64)
                    const float c1 = 0.011048543456039806f;   // 1/(sqrt(2)*64)
                    sm[OFF_TMP + 160*20 + ra] = p0a*c0;
                    sm[OFF_SP1 + ra*4 + 0] = pxa*c1;
                    sm[OFF_SP1 + ra*4 + 1] = pya*c1;
                    sm[OFF_SP1 + ra*4 + 2] = pza*c1;
                    sm[OFF_TMP + 160*20 + rb] = p0b*c0;
                    sm[OFF_SP1 + rb*4 + 0] = pxb*c1;
                    sm[OFF_SP1 + rb*4 + 1] = pyb*c1;
                    sm[OFF_SP1 + rb*4 + 2] = pzb*c1;
                }
            } else {
                // op3: n_k for 2 rows/thread
                int t2 = t - 256;
                int j = t2 & 31, rp = (t2 >> 5) * 2;
                float a[2][5] = {};
                const float* W = W_l2 + k*32*32;
                #pragma unroll 2
                for (int i = 0; i < 32; ++i) {
                    float w = __ldg(&W[i*32 + j]);
                    #pragma unroll
                    for (int m = 0; m < 5; ++m) {
                        float2 xv = *reinterpret_cast<const float2*>(&sm[OFF_XS + (i*5 + m)*20 + rp]);
                        a[0][m] += xv.x*w; a[1][m] += xv.y*w;
                    }
                }
                #pragma unroll
                for (int rr = 0; rr < 2; ++rr) {
                    float s2 = a[rr][0]*a[rr][0] + a[rr][1]*a[rr][1] + a[rr][2]*a[rr][2]
                             + a[rr][3]*a[rr][3] + a[rr][4]*a[rr][4];
                    sm[OFF_TMP + (128 + j)*20 + rp + rr] = sqrtf(s2)*0.17677669529663687f; // 1/sqrt(32)
                }
            }
        }
        __syncthreads();

        // ---- op5: s_tilde = [s_k|n_k|p0](161) @ Ws[k] + bs[k] ----
        {
            int c = t & 255, h = t >> 8;             // 2 groups of 8 rows
            float acc[8] = {};
            const float* W = Ws + k*161*256;
            #pragma unroll 4
            for (int i = 0; i < 160; ++i) {
                float w = __ldg(&W[i*256 + c]);
                const float4 t0 = *reinterpret_cast<const float4*>(&sm[OFF_TMP + i*20 + h*8]);
                const float4 t1 = *reinterpret_cast<const float4*>(&sm[OFF_TMP + i*20 + h*8 + 4]);
                acc[0] += t0.x*w; acc[1] += t0.y*w; acc[2] += t0.z*w; acc[3] += t0.w*w;
                acc[4] += t1.x*w; acc[5] += t1.y*w; acc[6] += t1.z*w; acc[7] += t1.w*w;
            }
            {   // i = 160 (p0 column)
                float w = __ldg(&W[160*256 + c]);
                const float4 t0 = *reinterpret_cast<const float4*>(&sm[OFF_TMP + 160*20 + h*8]);
                const float4 t1 = *reinterpret_cast<const float4*>(&sm[OFF_TMP + 160*20 + h*8 + 4]);
                acc[0] += t0.x*w; acc[1] += t0.y*w; acc[2] += t0.z*w; acc[3] += t0.w*w;
                acc[4] += t1.x*w; acc[5] += t1.y*w; acc[6] += t1.z*w; acc[7] += t1.w*w;
            }
            float bb = __ldg(&bs[k*256 + c]);
            #pragma unroll
            for (int rr = 0; rr < 8; ++rr)
                sm[OFF_SCUR + (h*8 + rr)*256 + c] = acc[rr] + bb;
        }

        // ---- op6: v1o, v1e -> Vcur ----
        {
            int j = t & 63, rg = t >> 6;
            float a[2][3] = {};
            const float* W = Wv1o + k*64*64;
            #pragma unroll 4
            for (int i = 0; i < 64; ++i) {
                float w = __ldg(&W[i*64 + j]);
                #pragma unroll
                for (int m = 0; m < 3; ++m) {
                    a[0][m] += vkbuf[(rg*2    )*192 + i*3 + m]*w;
                    a[1][m] += vkbuf[(rg*2 + 1)*192 + i*3 + m]*w;
                }
            }
            float we = __ldg(&Wv1e[k*64 + j]);
            #pragma unroll
            for (int rr = 0; rr < 2; ++rr) {
                int r = rg*2 + rr;
                #pragma unroll
                for (int m = 0; m < 3; ++m) {
                    sm[OFF_VCUR + r*384 + j*3 + m]       = a[rr][m]*0.125f;
                    sm[OFF_VCUR + r*384 + 192 + j*3 + m] = sm[OFF_SP1 + r*4 + m]*we;
                }
            }
        }
        __syncthreads();

        // ---- layernorm (warp per row) with fused m-norms; writes HBUF ----
        {
            int r = t >> 5, lane = t & 31;
            float s = 0.f, s2 = 0.f;
            #pragma unroll
            for (int c = lane; c < 384; c += 32) {
                float v;
                if (c < 256) v = sm[OFF_SCUR + r*256 + c];
                else {
                    int idx = c - 256;
                    float a = sm[OFF_VCUR + r*384 + idx*3];
                    float b = sm[OFF_VCUR + r*384 + idx*3 + 1];
                    float d = sm[OFF_VCUR + r*384 + idx*3 + 2];
                    v = sqrtf(a*a + b*b + d*d);
                    sm[OFF_MBUF + r*128 + idx] = v;
                }
                s += v; s2 += v*v;
            }
            #pragma unroll
            for (int off = 16; off > 0; off >>= 1) {
                s  += __shfl_xor_sync(0xffffffffu, s,  off);
                s2 += __shfl_xor_sync(0xffffffffu, s2, off);
            }
            float mu   = s  * (1.f/384.f);
            float var  = s2 * (1.f/384.f) - mu*mu;
            float rstd = rsqrtf(var + 1e-5f);
            #pragma unroll
            for (int c = lane; c < 384; c += 32) {
                float v = (c < 256) ? sm[OFF_SCUR + r*256 + c] : sm[OFF_MBUF + r*128 + c - 256];
                sm[OFF_HBUF + r*384 + c] = (v - mu)*rstd*sm[OFF_GB + c] + sm[OFF_GB + 384 + c];
            }
            if (lane == 0) sm[OFF_EV + r*4 + k] = 0.f;
        }
        __syncthreads();

        // ---- phase: MLP (warps 0-7, block GEMM) | spill S,V (warps 8-15) ----
        if (t < 256) {
            int c = t & 63, g = t >> 6;              // 4 groups of 4 rows
            float acc[4] = {};
            #pragma unroll 2
            for (int i = 0; i < 384; i += 4) {
                float w0 = __ldg(&Wm1[(i+0)*64 + c]);
                float w1 = __ldg(&Wm1[(i+1)*64 + c]);
                float w2 = __ldg(&Wm1[(i+2)*64 + c]);
                float w3 = __ldg(&Wm1[(i+3)*64 + c]);
                #pragma unroll
                for (int rr = 0; rr < 4; ++rr) {
                    const float4 hv = *reinterpret_cast<const float4*>(&sm[OFF_HBUF + (g*4 + rr)*384 + i]);
                    acc[rr] += hv.x*w0 + hv.y*w1 + hv.z*w2 + hv.w*w3;
                }
            }
            float wm2c = sm[OFF_WM2 + c];
            float b1c  = sm[OFF_BM1 + c];
            float ep[4];
            #pragma unroll
            for (int rr = 0; rr < 4; ++rr) {
                float a = acc[rr] + b1c;
                ep[rr] = a/(1.f + expf(-a)) * wm2c;
            }
            int lane = t & 31;
            #pragma unroll
            for (int off = 16; off > 0; off >>= 1)
                #pragma unroll
                for (int rr = 0; rr < 4; ++rr)
                    ep[rr] += __shfl_down_sync(0xffffffffu, ep[rr], off);
            if (lane == 0) {
                #pragma unroll
                for (int rr = 0; rr < 4; ++rr)
                    atomicAdd(&sm[OFF_EV + (g*4 + rr)*4 + k], ep[rr]);
            }
        } else {
            for (int idx = t - 256; idx < ROWS*640; idx += 256) {
                int r = idx / 640, c = idx % 640;
                float v = (c < 256) ? sm[OFF_SCUR + r*256 + c] : sm[OFF_VCUR + r*384 + c - 256];
                g_SV[(size_t)(r0 + r)*2560 + (size_t)k*640 + c] = v;
            }
        }

        { float* tp = vkbuf; vkbuf = vpbuf; vpbuf = tp; }
        __syncthreads();
    }

    // ---- softmax over K (bm2 cancels in softmax) ----
    if (t < ROWS) {
        float e0 = sm[OFF_EV + t*4 + 0], e1 = sm[OFF_EV + t*4 + 1];
        float e2 = sm[OFF_EV + t*4 + 2], e3 = sm[OFF_EV + t*4 + 3];
        float mx = fmaxf(fmaxf(e0, e1), fmaxf(e2, e3));
        float z0 = expf(e0 - mx), z1 = expf(e1 - mx), z2 = expf(e2 - mx), z3 = expf(e3 - mx);
        float inv = 1.f/(z0 + z1 + z2 + z3);
        g_alpha[(size_t)(r0 + t)*4 + 0] = z0*inv;
        g_alpha[(size_t)(r0 + t)*4 + 1] = z1*inv;
        g_alpha[(size_t)(r0 + t)*4 + 2] = z2*inv;
        g_alpha[(size_t)(r0 + t)*4 + 3] = z3*inv;
    }
}

// out = concat(flatten((alpha*S).sum(k)), flatten((alpha*V).sum(k)))
__global__ void fuse_k2(float* __restrict__ out)
{
    int r = blockIdx.x;
    int c = threadIdx.x;  // 640
    __shared__ float al[4];
    if (c < 4) al[c] = g_alpha[(size_t)r*4 + c];
    __syncthreads();
    const float* sv = g_SV + (size_t)r*2560;
    float acc = al[0]*sv[c] + al[1]*sv[640 + c] + al[2]*sv[1280 + c] + al[3]*sv[1920 + c];
    if (c < 256) out[(size_t)r*256 + c] = acc;
    else         out[(size_t)NTOK*256 + (size_t)r*384 + (c - 256)] = acc;
}

extern "C" void kernel_launch(void* const* d_in, const int* in_sizes, int n_in,
                              void* d_out, int out_size)
{
    (void)in_sizes; (void)n_in; (void)out_size;
    cudaFuncSetAttribute(fuse_k1, cudaFuncAttributeMaxDynamicSharedMemorySize, SMEM_BYTES);

    fuse_k1<<<NTOK/ROWS, NTHR, SMEM_BYTES>>>(
        (const float*)d_in[0],  (const float*)d_in[1],  (const float*)d_in[2],
        (const float*)d_in[3],  (const float*)d_in[4],  (const float*)d_in[5],
        (const float*)d_in[6],  (const float*)d_in[7],  (const float*)d_in[8],
        (const float*)d_in[9],  (const float*)d_in[10], (const float*)d_in[11],
        (const float*)d_in[12], (const float*)d_in[13], (const float*)d_in[14],
        (const float*)d_in[15], (const float*)d_in[16], (const float*)d_in[17],
        (const float*)d_in[18]);

    fuse_k2<<<NTOK, 640>>>((float*)d_out);
}

// round 6
// speedup vs baseline: 1.4092x; 1.1170x over previous
#include <cuda_runtime.h>
#include <math.h>

#define NTOK 80000
#define KK   4
#define ROWS 16
#define NTHR 512

// ---------------- smem layout (float offsets), ~106 KB -> 2 CTAs/SM ----------------
constexpr int OFF_SCUR = 0;                  // 16*256 = 4096
constexpr int OFF_VCUR = OFF_SCUR + 4096;    // 16*384 = 6144 (also holds U0/U1 during op4)
constexpr int OFF_XS   = OFF_VCUR + 6144;    // transposed x, stride 20: 192*20 = 3840
constexpr int OFF_TMP  = OFF_XS   + 3840;    // transposed [s_k|n_k|p0], stride 20: 161*20 -> 3232
constexpr int OFF_VKA  = OFF_TMP  + 3232;    // 16*192 = 3072
constexpr int OFF_VKB  = OFF_VKA  + 3072;    // 16*192 = 3072
constexpr int OFF_MBUF = OFF_VKB  + 3072;    // 16*128 = 2048 (m-norms; reused as MLP partial buf)
constexpr int OFF_GB   = OFF_MBUF + 2048;    // gamma 384 + beta 384
constexpr int OFF_BM1  = OFF_GB   + 768;     // 64
constexpr int OFF_WM2  = OFF_BM1  + 64;      // 64
constexpr int OFF_SP1  = OFF_WM2  + 64;      // 16*4
constexpr int OFF_EV   = OFF_SP1  + 64;      // 16*4
constexpr int SMEM_FLOATS = OFF_EV + 64;     // 26528 floats
constexpr int SMEM_BYTES  = SMEM_FLOATS * 4; // 106112 B -> 2 blocks/SM
// hbuf (normalized layernorm output, 16*384=6144) overlays freed XS+TMP (7072)
constexpr int OFF_HBUF = OFF_XS;

// ---------------- global scratch (no allocs allowed) ----------------
__device__ __align__(16) float g_SV[(size_t)NTOK * 2560];  // [row][k][640] : S(256) then V(384)
__device__ __align__(16) float g_alpha[(size_t)NTOK * KK];

__global__ void __launch_bounds__(NTHR, 2)
fuse_k1(const float* __restrict__ x0, const float* __restrict__ x1,
        const float* __restrict__ x2, const float* __restrict__ x3,
        const float* __restrict__ W_l0, const float* __restrict__ W_l1,
        const float* __restrict__ W_l2, const float* __restrict__ W_tp0,
        const float* __restrict__ W_tp1, const float* __restrict__ Ws,
        const float* __restrict__ bs, const float* __restrict__ Wv1o,
        const float* __restrict__ Wv1e, const float* __restrict__ gamma,
        const float* __restrict__ beta, const float* __restrict__ Wm1,
        const float* __restrict__ bm1, const float* __restrict__ Wm2,
        const float* __restrict__ bm2)
{
    extern __shared__ float sm[];
    const int t  = threadIdx.x;
    const int r0 = blockIdx.x * ROWS;

    // stage small block-resident constants
    for (int i = t; i < 384; i += NTHR) { sm[OFF_GB + i] = gamma[i]; sm[OFF_GB + 384 + i] = beta[i]; }
    if (t < 64) { sm[OFF_BM1 + t] = bm1[t]; sm[OFF_WM2 + t] = Wm2[t]; }
    __syncthreads();

    const float* xs_ptr[KK] = {x0, x1, x2, x3};
    float* vkbuf = sm + OFF_VKA;
    float* vpbuf = sm + OFF_VKB;

    for (int k = 0; k < KK; ++k) {
        const float* xg = xs_ptr[k];

        // ---- stage x_s (transposed, stride 20) ----
        for (int idx = t; idx < ROWS*128; idx += NTHR) {
            int r = idx >> 7, c = idx & 127;
            sm[OFF_XS + c*20 + r] = xg[(size_t)(r0 + r)*480 + c];
        }
        __syncthreads();

        // ---- op1: s_k[j] = inv0 * sum_i x_s[i] W_l0[k][i][j] ----
        {
            int j = t & 127, rq = t >> 7;            // 4 groups of 4 rows
            float a0 = 0, a1 = 0, a2 = 0, a3 = 0;
            const float* W = W_l0 + k*128*128;
            #pragma unroll 4
            for (int i = 0; i < 128; ++i) {
                float w = __ldg(&W[i*128 + j]);
                const float4 xv = *reinterpret_cast<const float4*>(&sm[OFF_XS + i*20 + rq*4]);
                a0 += xv.x*w; a1 += xv.y*w; a2 += xv.z*w; a3 += xv.w*w;
            }
            const float s = 0.08838834764831845f;    // 1/sqrt(128)
            sm[OFF_TMP + j*20 + rq*4 + 0] = a0*s;
            sm[OFF_TMP + j*20 + rq*4 + 1] = a1*s;
            sm[OFF_TMP + j*20 + rq*4 + 2] = a2*s;
            sm[OFF_TMP + j*20 + rq*4 + 3] = a3*s;
        }
        __syncthreads();

        // ---- stage x_v (192 cols) ----
        for (int idx = t; idx < ROWS*192; idx += NTHR) {
            int r = idx / 192, c = idx % 192;
            sm[OFF_XS + c*20 + r] = xg[(size_t)(r0 + r)*480 + 128 + c];
        }
        __syncthreads();

        // ---- op2: v_k[j][m] = inv1 * sum_i x_v[i][m] W_l1[k][i][j] ----
        {
            int j = t & 63, rg = t >> 6;             // 8 groups of 2 rows
            float a[2][3] = {};
            const float* W = W_l1 + k*64*64;
            #pragma unroll 4
            for (int i = 0; i < 64; ++i) {
                float w = __ldg(&W[i*64 + j]);
                #pragma unroll
                for (int m = 0; m < 3; ++m) {
                    float2 xv = *reinterpret_cast<const float2*>(&sm[OFF_XS + (i*3 + m)*20 + rg*2]);
                    a[0][m] += xv.x*w; a[1][m] += xv.y*w;
                }
            }
            #pragma unroll
            for (int rr = 0; rr < 2; ++rr)
                #pragma unroll
                for (int m = 0; m < 3; ++m)
                    vkbuf[(rg*2 + rr)*192 + j*3 + m] = a[rr][m]*0.125f;
        }
        __syncthreads();

        // ---- stage x_T (160 cols) ----
        for (int idx = t; idx < ROWS*160; idx += NTHR) {
            int r = idx / 160, c = idx % 160;
            sm[OFF_XS + c*20 + r] = xg[(size_t)(r0 + r)*480 + 320 + c];
        }
        __syncthreads();

        // ---- op3 (all threads): n_k[j] = inv2 * || sum_i x_T[i][:] W_l2[k][i][j] || ----
        {
            int j = t & 31, r = t >> 5;              // 1 row/thread, 16 rows x 32 j
            float a[5] = {};
            const float* W = W_l2 + k*32*32;
            #pragma unroll 4
            for (int i = 0; i < 32; ++i) {
                float w = __ldg(&W[i*32 + j]);
                #pragma unroll
                for (int m = 0; m < 5; ++m) a[m] += sm[OFF_XS + (i*5 + m)*20 + r]*w;
            }
            float s2 = a[0]*a[0] + a[1]*a[1] + a[2]*a[2] + a[3]*a[3] + a[4]*a[4];
            sm[OFF_TMP + (128 + j)*20 + r] = sqrtf(s2)*0.17677669529663687f;  // 1/sqrt(32)
        }

        // ---- op4-GEMM (all threads): U0 = v_k @ W_tp0, U1 = v_k @ W_tp1 -> VCUR ----
        if (k > 0) {
            int j = t & 63, rg = t >> 6;
            int ra = rg*2, rb = rg*2 + 1;
            float u0a[3] = {}, u0b[3] = {}, u1a[3] = {}, u1b[3] = {};
            #pragma unroll 2
            for (int i = 0; i < 64; ++i) {
                float w0 = __ldg(&W_tp0[i*64 + j]);
                float w1 = __ldg(&W_tp1[i*64 + j]);
                #pragma unroll
                for (int m = 0; m < 3; ++m) {
                    float va = vkbuf[ra*192 + i*3 + m];
                    float vb = vkbuf[rb*192 + i*3 + m];
                    u0a[m] += va*w0; u1a[m] += va*w1;
                    u0b[m] += vb*w0; u1b[m] += vb*w1;
                }
            }
            #pragma unroll
            for (int m = 0; m < 3; ++m) {
                sm[OFF_VCUR + ra*384 +       j*3 + m] = u0a[m];
                sm[OFF_VCUR + ra*384 + 192 + j*3 + m] = u1a[m];
                sm[OFF_VCUR + rb*384 +       j*3 + m] = u0b[m];
                sm[OFF_VCUR + rb*384 + 192 + j*3 + m] = u1b[m];
            }
        }
        __syncthreads();

        // ---- op4-reduce: p0/p1 per row (warps 0-7, 2 rows/warp) ----
        if (k > 0) {
            int w = t >> 5, lane = t & 31;
            if (w < 8) {
                int ra = 2*w, rb = 2*w + 1;
                float p0a=0,pxa=0,pya=0,pza=0, p0b=0,pxb=0,pyb=0,pzb=0;
                #pragma unroll
                for (int jj = 0; jj < 2; ++jj) {
                    int j = jj*32 + lane;
                    const float* u0 = &sm[OFF_VCUR + ra*384 +       j*3];
                    const float* u1 = &sm[OFF_VCUR + ra*384 + 192 + j*3];
                    const float* vp = &vpbuf[ra*192 + j*3];
                    p0a += u0[0]*vp[0] + u0[1]*vp[1] + u0[2]*vp[2];
                    pxa += u1[1]*vp[2] - u1[2]*vp[1];
                    pya += u1[2]*vp[0] - u1[0]*vp[2];
                    pza += u1[0]*vp[1] - u1[1]*vp[0];
                    u0 = &sm[OFF_VCUR + rb*384 +       j*3];
                    u1 = &sm[OFF_VCUR + rb*384 + 192 + j*3];
                    vp = &vpbuf[rb*192 + j*3];
                    p0b += u0[0]*vp[0] + u0[1]*vp[1] + u0[2]*vp[2];
                    pxb += u1[1]*vp[2] - u1[2]*vp[1];
                    pyb += u1[2]*vp[0] - u1[0]*vp[2];
                    pzb += u1[0]*vp[1] - u1[1]*vp[0];
                }
                #pragma unroll
                for (int off = 16; off > 0; off >>= 1) {
                    p0a += __shfl_down_sync(0xffffffffu, p0a, off);
                    pxa += __shfl_down_sync(0xffffffffu, pxa, off);
                    pya += __shfl_down_sync(0xffffffffu, pya, off);
                    pza += __shfl_down_sync(0xffffffffu, pza, off);
                    p0b += __shfl_down_sync(0xffffffffu, p0b, off);
                    pxb += __shfl_down_sync(0xffffffffu, pxb, off);
                    pyb += __shfl_down_sync(0xffffffffu, pyb, off);
                    pzb += __shfl_down_sync(0xffffffffu, pzb, off);
                }
                if (lane == 0) {
                    const float c0 = 0.009021097956087905f;   // 1/(sqrt(3)*64)
                    const float c1 = 0.011048543456039806f;   // 1/(sqrt(2)*64)
                    sm[OFF_TMP + 160*20 + ra] = p0a*c0;
                    sm[OFF_SP1 + ra*4 + 0] = pxa*c1;
                    sm[OFF_SP1 + ra*4 + 1] = pya*c1;
                    sm[OFF_SP1 + ra*4 + 2] = pza*c1;
                    sm[OFF_TMP + 160*20 + rb] = p0b*c0;
                    sm[OFF_SP1 + rb*4 + 0] = pxb*c1;
                    sm[OFF_SP1 + rb*4 + 1] = pyb*c1;
                    sm[OFF_SP1 + rb*4 + 2] = pzb*c1;
                }
            }
        } else {
            if (t < 16) {
                sm[OFF_TMP + 160*20 + t] = 0.f;
                sm[OFF_SP1 + t*4 + 0] = 0.f;
                sm[OFF_SP1 + t*4 + 1] = 0.f;
                sm[OFF_SP1 + t*4 + 2] = 0.f;
            }
        }
        __syncthreads();

        // ---- op5: s_tilde = [s_k|n_k|p0](161) @ Ws[k] + bs[k] (2 cols/thread) ----
        {
            int c2 = (t & 127) * 2, h4 = t >> 7;     // 4 groups of 4 rows
            float accA[4] = {}, accB[4] = {};
            const float* W = Ws + k*161*256;
            #pragma unroll 4
            for (int i = 0; i < 161; ++i) {
                const float2 w = *reinterpret_cast<const float2*>(&W[i*256 + c2]);
                const float4 xv = *reinterpret_cast<const float4*>(&sm[OFF_TMP + i*20 + h4*4]);
                accA[0] += xv.x*w.x; accA[1] += xv.y*w.x; accA[2] += xv.z*w.x; accA[3] += xv.w*w.x;
                accB[0] += xv.x*w.y; accB[1] += xv.y*w.y; accB[2] += xv.z*w.y; accB[3] += xv.w*w.y;
            }
            const float2 bb = *reinterpret_cast<const float2*>(&bs[k*256 + c2]);
            #pragma unroll
            for (int rr = 0; rr < 4; ++rr) {
                float2 o; o.x = accA[rr] + bb.x; o.y = accB[rr] + bb.y;
                *reinterpret_cast<float2*>(&sm[OFF_SCUR + (h4*4 + rr)*256 + c2]) = o;
            }
        }

        // ---- op6: v1o, v1e -> Vcur ----
        {
            int j = t & 63, rg = t >> 6;
            float a[2][3] = {};
            const float* W = Wv1o + k*64*64;
            #pragma unroll 4
            for (int i = 0; i < 64; ++i) {
                float w = __ldg(&W[i*64 + j]);
                #pragma unroll
                for (int m = 0; m < 3; ++m) {
                    a[0][m] += vkbuf[(rg*2    )*192 + i*3 + m]*w;
                    a[1][m] += vkbuf[(rg*2 + 1)*192 + i*3 + m]*w;
                }
            }
            float we = __ldg(&Wv1e[k*64 + j]);
            #pragma unroll
            for (int rr = 0; rr < 2; ++rr) {
                int r = rg*2 + rr;
                #pragma unroll
                for (int m = 0; m < 3; ++m) {
                    sm[OFF_VCUR + r*384 + j*3 + m]       = a[rr][m]*0.125f;
                    sm[OFF_VCUR + r*384 + 192 + j*3 + m] = sm[OFF_SP1 + r*4 + m]*we;
                }
            }
        }
        __syncthreads();

        // ---- layernorm (warp per row) w/ fused m-norms; writes HBUF. Then float4 spill. ----
        {
            int r = t >> 5, lane = t & 31;
            float s = 0.f, s2 = 0.f;
            #pragma unroll
            for (int c = lane; c < 384; c += 32) {
                float v;
                if (c < 256) v = sm[OFF_SCUR + r*256 + c];
                else {
                    int idx = c - 256;
                    float a = sm[OFF_VCUR + r*384 + idx*3];
                    float b = sm[OFF_VCUR + r*384 + idx*3 + 1];
                    float d = sm[OFF_VCUR + r*384 + idx*3 + 2];
                    v = sqrtf(a*a + b*b + d*d);
                    sm[OFF_MBUF + r*128 + idx] = v;
                }
                s += v; s2 += v*v;
            }
            #pragma unroll
            for (int off = 16; off > 0; off >>= 1) {
                s  += __shfl_xor_sync(0xffffffffu, s,  off);
                s2 += __shfl_xor_sync(0xffffffffu, s2, off);
            }
            float mu   = s  * (1.f/384.f);
            float var  = s2 * (1.f/384.f) - mu*mu;
            float rstd = rsqrtf(var + 1e-5f);
            #pragma unroll
            for (int c = lane; c < 384; c += 32) {
                float v = (c < 256) ? sm[OFF_SCUR + r*256 + c] : sm[OFF_MBUF + r*128 + c - 256];
                sm[OFF_HBUF + r*384 + c] = (v - mu)*rstd*sm[OFF_GB + c] + sm[OFF_GB + 384 + c];
            }
            if (lane == 0) sm[OFF_EV + r*4 + k] = 0.f;
        }
        // spill S,V (float4, all threads; reads SCUR/VCUR which are stable)
        for (int idx = t; idx < ROWS*160; idx += NTHR) {
            int r = idx / 160, q = idx - r*160;
            float4 v;
            if (q < 64) v = *reinterpret_cast<const float4*>(&sm[OFF_SCUR + r*256 + q*4]);
            else        v = *reinterpret_cast<const float4*>(&sm[OFF_VCUR + r*384 + (q - 64)*4]);
            *reinterpret_cast<float4*>(&g_SV[(size_t)(r0 + r)*2560 + (size_t)k*640 + q*4]) = v;
        }
        __syncthreads();

        // ---- MLP: all 512 threads, i-dimension split in halves ----
        {
            int c = t & 63, g = (t >> 6) & 3, hh = t >> 8;
            float acc[4] = {};
            const float* Wp = Wm1 + hh*192*64;
            const int ibase = hh*192;
            #pragma unroll 2
            for (int i = 0; i < 192; i += 4) {
                float w0 = __ldg(&Wp[(i+0)*64 + c]);
                float w1 = __ldg(&Wp[(i+1)*64 + c]);
                float w2 = __ldg(&Wp[(i+2)*64 + c]);
                float w3 = __ldg(&Wp[(i+3)*64 + c]);
                #pragma unroll
                for (int rr = 0; rr < 4; ++rr) {
                    const float4 hv = *reinterpret_cast<const float4*>(&sm[OFF_HBUF + (g*4 + rr)*384 + ibase + i]);
                    acc[rr] += hv.x*w0 + hv.y*w1 + hv.z*w2 + hv.w*w3;
                }
            }
            if (hh == 1) {
                float4 p; p.x = acc[0]; p.y = acc[1]; p.z = acc[2]; p.w = acc[3];
                *reinterpret_cast<float4*>(&sm[OFF_MBUF + (t - 256)*4]) = p;
            }
            __syncthreads();
            if (hh == 0) {
                const float4 p = *reinterpret_cast<const float4*>(&sm[OFF_MBUF + t*4]);
                acc[0] += p.x; acc[1] += p.y; acc[2] += p.z; acc[3] += p.w;
                float wm2c = sm[OFF_WM2 + c];
                float b1c  = sm[OFF_BM1 + c];
                float ep[4];
                #pragma unroll
                for (int rr = 0; rr < 4; ++rr) {
                    float a = acc[rr] + b1c;
                    ep[rr] = a/(1.f + expf(-a)) * wm2c;
                }
                int lane = t & 31;
                #pragma unroll
                for (int off = 16; off > 0; off >>= 1)
                    #pragma unroll
                    for (int rr = 0; rr < 4; ++rr)
                        ep[rr] += __shfl_down_sync(0xffffffffu, ep[rr], off);
                if (lane == 0) {
                    #pragma unroll
                    for (int rr = 0; rr < 4; ++rr)
                        atomicAdd(&sm[OFF_EV + (g*4 + rr)*4 + k], ep[rr]);
                }
            }
        }

        { float* tp = vkbuf; vkbuf = vpbuf; vpbuf = tp; }
        __syncthreads();
    }

    // ---- softmax over K (bm2 cancels in softmax) ----
    if (t < ROWS) {
        float e0 = sm[OFF_EV + t*4 + 0], e1 = sm[OFF_EV + t*4 + 1];
        float e2 = sm[OFF_EV + t*4 + 2], e3 = sm[OFF_EV + t*4 + 3];
        float mx = fmaxf(fmaxf(e0, e1), fmaxf(e2, e3));
        float z0 = expf(e0 - mx), z1 = expf(e1 - mx), z2 = expf(e2 - mx), z3 = expf(e3 - mx);
        float inv = 1.f/(z0 + z1 + z2 + z3);
        g_alpha[(size_t)(r0 + t)*4 + 0] = z0*inv;
        g_alpha[(size_t)(r0 + t)*4 + 1] = z1*inv;
        g_alpha[(size_t)(r0 + t)*4 + 2] = z2*inv;
        g_alpha[(size_t)(r0 + t)*4 + 3] = z3*inv;
    }
}

// out = concat(flatten((alpha*S).sum(k)), flatten((alpha*V).sum(k)))
// 2 rows per 320-thread block; one float4 output per thread.
__global__ void fuse_k2(float* __restrict__ out)
{
    __shared__ float al[8];
    const int t  = threadIdx.x;              // 0..319
    const int rb = blockIdx.x * 2;
    if (t < 8) al[t] = g_alpha[(size_t)rb*4 + t];
    __syncthreads();
    const int half = (t >= 160) ? 1 : 0;
    const int q = t - half*160;
    const int r = rb + half;
    const float* sv = g_SV + (size_t)r*2560 + q*4;
    const float a0 = al[half*4 + 0], a1 = al[half*4 + 1];
    const float a2 = al[half*4 + 2], a3 = al[half*4 + 3];
    const float4 v0 = *reinterpret_cast<const float4*>(sv);
    const float4 v1 = *reinterpret_cast<const float4*>(sv + 640);
    const float4 v2 = *reinterpret_cast<const float4*>(sv + 1280);
    const float4 v3 = *reinterpret_cast<const float4*>(sv + 1920);
    float4 o;
    o.x = a0*v0.x + a1*v1.x + a2*v2.x + a3*v3.x;
    o.y = a0*v0.y + a1*v1.y + a2*v2.y + a3*v3.y;
    o.z = a0*v0.z + a1*v1.z + a2*v2.z + a3*v3.z;
    o.w = a0*v0.w + a1*v1.w + a2*v2.w + a3*v3.w;
    if (q < 64) *reinterpret_cast<float4*>(&out[(size_t)r*256 + q*4]) = o;
    else        *reinterpret_cast<float4*>(&out[(size_t)NTOK*256 + (size_t)r*384 + (q - 64)*4]) = o;
}

extern "C" void kernel_launch(void* const* d_in, const int* in_sizes, int n_in,
                              void* d_out, int out_size)
{
    (void)in_sizes; (void)n_in; (void)out_size;
    cudaFuncSetAttribute(fuse_k1, cudaFuncAttributeMaxDynamicSharedMemorySize, SMEM_BYTES);

    fuse_k1<<<NTOK/ROWS, NTHR, SMEM_BYTES>>>(
        (const float*)d_in[0],  (const float*)d_in[1],  (const float*)d_in[2],
        (const float*)d_in[3],  (const float*)d_in[4],  (const float*)d_in[5],
        (const float*)d_in[6],  (const float*)d_in[7],  (const float*)d_in[8],
        (const float*)d_in[9],  (const float*)d_in[10], (const float*)d_in[11],
        (const float*)d_in[12], (const float*)d_in[13], (const float*)d_in[14],
        (const float*)d_in[15], (const float*)d_in[16], (const float*)d_in[17],
        (const float*)d_in[18]);

    fuse_k2<<<NTOK/2, 320>>>((float*)d_out);
}

// round 7
// speedup vs baseline: 1.4194x; 1.0073x over previous
#include <cuda_runtime.h>
#include <math.h>

#define NTOK 80000
#define KK   4
#define ROWS 16
#define NTHR 512

typedef unsigned long long ull;

// ---------------- f32x2 packed helpers ----------------
__device__ __forceinline__ ull pk2(float lo, float hi) {
    ull r;
    asm("mov.b64 %0, {%1, %2};" : "=l"(r) : "r"(__float_as_uint(lo)), "r"(__float_as_uint(hi)));
    return r;
}
__device__ __forceinline__ void upk2(float& lo, float& hi, ull v) {
    unsigned int a, b;
    asm("mov.b64 {%0, %1}, %2;" : "=r"(a), "=r"(b) : "l"(v));
    lo = __uint_as_float(a); hi = __uint_as_float(b);
}
__device__ __forceinline__ ull ffma2(ull a, ull b, ull c) {
    ull d;
    asm("fma.rn.f32x2 %0, %1, %2, %3;" : "=l"(d) : "l"(a), "l"(b), "l"(c));
    return d;
}
__device__ __forceinline__ ull fmul2(ull a, ull b) {
    ull d;
    asm("mul.rn.f32x2 %0, %1, %2;" : "=l"(d) : "l"(a), "l"(b));
    return d;
}

// ---------------- smem layout (float offsets), ~109 KB -> 2 CTAs/SM ----------------
constexpr int OFF_SCUR = 0;                  // 16*256 = 4096 (U1_T scratch during op4)
constexpr int OFF_VCUR = OFF_SCUR + 4096;    // 16*384 = 6144 (U0_T scratch during op4)
constexpr int OFF_XS   = OFF_VCUR + 6144;    // transposed x, stride 20: 192*20 = 3840
constexpr int OFF_TMP  = OFF_XS   + 3840;    // transposed [s_k|n_k|p0], stride 20: 161*20 -> 3232
constexpr int OFF_VKA  = OFF_TMP  + 3232;    // transposed v_k, stride 18: 192*18 = 3456
constexpr int OFF_VKB  = OFF_VKA  + 3456;    // 3456
constexpr int OFF_MBUF = OFF_VKB  + 3456;    // 16*128 = 2048 (m-norms; MLP partial buf)
constexpr int OFF_GB   = OFF_MBUF + 2048;    // gamma 384 + beta 384
constexpr int OFF_BM1  = OFF_GB   + 768;     // 64
constexpr int OFF_WM2  = OFF_BM1  + 64;      // 64
constexpr int OFF_SP1  = OFF_WM2  + 64;      // 16*4
constexpr int OFF_EV   = OFF_SP1  + 64;      // 16*4
constexpr int SMEM_FLOATS = OFF_EV + 64;     // 27296 floats
constexpr int SMEM_BYTES  = SMEM_FLOATS * 4; // 109184 B -> 2 blocks/SM
// hbuf (row-major LN output, 16*384=6144) overlays freed XS+TMP (7072)
constexpr int OFF_HBUF = OFF_XS;

// ---------------- global scratch (no allocs allowed) ----------------
__device__ __align__(16) float g_SV[(size_t)NTOK * 2560];  // [row][k][640] : S(256) then V(384)
__device__ __align__(16) float g_alpha[(size_t)NTOK * KK];

__global__ void __launch_bounds__(NTHR, 2)
fuse_k1(const float* __restrict__ x0, const float* __restrict__ x1,
        const float* __restrict__ x2, const float* __restrict__ x3,
        const float* __restrict__ W_l0, const float* __restrict__ W_l1,
        const float* __restrict__ W_l2, const float* __restrict__ W_tp0,
        const float* __restrict__ W_tp1, const float* __restrict__ Ws,
        const float* __restrict__ bs, const float* __restrict__ Wv1o,
        const float* __restrict__ Wv1e, const float* __restrict__ gamma,
        const float* __restrict__ beta, const float* __restrict__ Wm1,
        const float* __restrict__ bm1, const float* __restrict__ Wm2,
        const float* __restrict__ bm2)
{
    extern __shared__ float sm[];
    const int t  = threadIdx.x;
    const int r0 = blockIdx.x * ROWS;

    // stage small block-resident constants
    for (int i = t; i < 384; i += NTHR) { sm[OFF_GB + i] = gamma[i]; sm[OFF_GB + 384 + i] = beta[i]; }
    if (t < 64) { sm[OFF_BM1 + t] = bm1[t]; sm[OFF_WM2 + t] = Wm2[t]; }
    __syncthreads();

    const float* xs_ptr[KK] = {x0, x1, x2, x3};
    float* vkbuf = sm + OFF_VKA;   // transposed [(j*3+m)*18 + r]
    float* vpbuf = sm + OFF_VKB;

    for (int k = 0; k < KK; ++k) {
        const float* xg = xs_ptr[k];

        // ---- stage x_s (transposed, stride 20) ----
        for (int idx = t; idx < ROWS*128; idx += NTHR) {
            int r = idx >> 7, c = idx & 127;
            sm[OFF_XS + c*20 + r] = xg[(size_t)(r0 + r)*480 + c];
        }
        __syncthreads();

        // ---- op1: s_k[j] = inv0 * sum_i x_s[i] W_l0[k][i][j]  (packed rows) ----
        {
            int j = t & 127, rq = t >> 7;            // 4 groups of 4 rows
            ull a01 = 0, a23 = 0;
            const float* W = W_l0 + k*128*128;
            #pragma unroll 4
            for (int i = 0; i < 128; ++i) {
                float w = __ldg(&W[i*128 + j]);
                ull ww = pk2(w, w);
                const ulonglong2 xv = *reinterpret_cast<const ulonglong2*>(&sm[OFF_XS + i*20 + rq*4]);
                a01 = ffma2(xv.x, ww, a01);
                a23 = ffma2(xv.y, ww, a23);
            }
            const ull ss = pk2(0.08838834764831845f, 0.08838834764831845f);  // 1/sqrt(128)
            *reinterpret_cast<ull*>(&sm[OFF_TMP + j*20 + rq*4    ]) = fmul2(a01, ss);
            *reinterpret_cast<ull*>(&sm[OFF_TMP + j*20 + rq*4 + 2]) = fmul2(a23, ss);
        }
        __syncthreads();

        // ---- stage x_v (192 cols) ----
        for (int idx = t; idx < ROWS*192; idx += NTHR) {
            int r = idx / 192, c = idx % 192;
            sm[OFF_XS + c*20 + r] = xg[(size_t)(r0 + r)*480 + 128 + c];
        }
        __syncthreads();

        // ---- op2: v_k (packed row pairs) -> vk_T stride 18 ----
        {
            int j = t & 63, rg = t >> 6;             // 8 groups of 2 rows
            ull a0 = 0, a1 = 0, a2 = 0;
            const float* W = W_l1 + k*64*64;
            #pragma unroll 4
            for (int i = 0; i < 64; ++i) {
                float w = __ldg(&W[i*64 + j]);
                ull ww = pk2(w, w);
                a0 = ffma2(*reinterpret_cast<const ull*>(&sm[OFF_XS + (i*3 + 0)*20 + rg*2]), ww, a0);
                a1 = ffma2(*reinterpret_cast<const ull*>(&sm[OFF_XS + (i*3 + 1)*20 + rg*2]), ww, a1);
                a2 = ffma2(*reinterpret_cast<const ull*>(&sm[OFF_XS + (i*3 + 2)*20 + rg*2]), ww, a2);
            }
            const ull ei = pk2(0.125f, 0.125f);
            *reinterpret_cast<ull*>(&vkbuf[(j*3 + 0)*18 + rg*2]) = fmul2(a0, ei);
            *reinterpret_cast<ull*>(&vkbuf[(j*3 + 1)*18 + rg*2]) = fmul2(a1, ei);
            *reinterpret_cast<ull*>(&vkbuf[(j*3 + 2)*18 + rg*2]) = fmul2(a2, ei);
        }
        __syncthreads();

        // ---- stage x_T (160 cols) ----
        for (int idx = t; idx < ROWS*160; idx += NTHR) {
            int r = idx / 160, c = idx % 160;
            sm[OFF_XS + c*20 + r] = xg[(size_t)(r0 + r)*480 + 320 + c];
        }
        __syncthreads();

        // ---- op3 (all threads): n_k into TMP ----
        {
            int j = t & 31, r = t >> 5;
            float a[5] = {};
            const float* W = W_l2 + k*32*32;
            #pragma unroll 4
            for (int i = 0; i < 32; ++i) {
                float w = __ldg(&W[i*32 + j]);
                #pragma unroll
                for (int m = 0; m < 5; ++m) a[m] += sm[OFF_XS + (i*5 + m)*20 + r]*w;
            }
            float s2 = a[0]*a[0] + a[1]*a[1] + a[2]*a[2] + a[3]*a[3] + a[4]*a[4];
            sm[OFF_TMP + (128 + j)*20 + r] = sqrtf(s2)*0.17677669529663687f;  // 1/sqrt(32)
        }

        // ---- op4-GEMM (all threads, packed): U0_T -> VCUR, U1_T -> SCUR ----
        if (k > 0) {
            int j = t & 63, rg = t >> 6;
            ull u0[3] = {}, u1[3] = {};
            #pragma unroll 2
            for (int i = 0; i < 64; ++i) {
                float w0 = __ldg(&W_tp0[i*64 + j]);
                float w1 = __ldg(&W_tp1[i*64 + j]);
                ull ww0 = pk2(w0, w0), ww1 = pk2(w1, w1);
                #pragma unroll
                for (int m = 0; m < 3; ++m) {
                    ull vp = *reinterpret_cast<const ull*>(&vkbuf[(i*3 + m)*18 + rg*2]);
                    u0[m] = ffma2(vp, ww0, u0[m]);
                    u1[m] = ffma2(vp, ww1, u1[m]);
                }
            }
            #pragma unroll
            for (int m = 0; m < 3; ++m) {
                *reinterpret_cast<ull*>(&sm[OFF_VCUR + (j*3 + m)*18 + rg*2]) = u0[m];
                *reinterpret_cast<ull*>(&sm[OFF_SCUR + (j*3 + m)*18 + rg*2]) = u1[m];
            }
        }
        __syncthreads();

        // ---- op4-reduce: p0/p1 per row (warps 0-7, 2 rows/warp) ----
        if (k > 0) {
            int w = t >> 5, lane = t & 31;
            if (w < 8) {
                int ra = 2*w, rb = 2*w + 1;
                float p0a=0,pxa=0,pya=0,pza=0, p0b=0,pxb=0,pyb=0,pzb=0;
                #pragma unroll
                for (int jj = 0; jj < 2; ++jj) {
                    int j = jj*32 + lane;
                    float u00 = sm[OFF_VCUR + (j*3+0)*18 + ra];
                    float u01 = sm[OFF_VCUR + (j*3+1)*18 + ra];
                    float u02 = sm[OFF_VCUR + (j*3+2)*18 + ra];
                    float u10 = sm[OFF_SCUR + (j*3+0)*18 + ra];
                    float u11 = sm[OFF_SCUR + (j*3+1)*18 + ra];
                    float u12 = sm[OFF_SCUR + (j*3+2)*18 + ra];
                    float vx = vpbuf[(j*3+0)*18 + ra];
                    float vy = vpbuf[(j*3+1)*18 + ra];
                    float vz = vpbuf[(j*3+2)*18 + ra];
                    p0a += u00*vx + u01*vy + u02*vz;
                    pxa += u11*vz - u12*vy;
                    pya += u12*vx - u10*vz;
                    pza += u10*vy - u11*vx;
                    u00 = sm[OFF_VCUR + (j*3+0)*18 + rb];
                    u01 = sm[OFF_VCUR + (j*3+1)*18 + rb];
                    u02 = sm[OFF_VCUR + (j*3+2)*18 + rb];
                    u10 = sm[OFF_SCUR + (j*3+0)*18 + rb];
                    u11 = sm[OFF_SCUR + (j*3+1)*18 + rb];
                    u12 = sm[OFF_SCUR + (j*3+2)*18 + rb];
                    vx = vpbuf[(j*3+0)*18 + rb];
                    vy = vpbuf[(j*3+1)*18 + rb];
                    vz = vpbuf[(j*3+2)*18 + rb];
                    p0b += u00*vx + u01*vy + u02*vz;
                    pxb += u11*vz - u12*vy;
                    pyb += u12*vx - u10*vz;
                    pzb += u10*vy - u11*vx;
                }
                #pragma unroll
                for (int off = 16; off > 0; off >>= 1) {
                    p0a += __shfl_down_sync(0xffffffffu, p0a, off);
                    pxa += __shfl_down_sync(0xffffffffu, pxa, off);
                    pya += __shfl_down_sync(0xffffffffu, pya, off);
                    pza += __shfl_down_sync(0xffffffffu, pza, off);
                    p0b += __shfl_down_sync(0xffffffffu, p0b, off);
                    pxb += __shfl_down_sync(0xffffffffu, pxb, off);
                    pyb += __shfl_down_sync(0xffffffffu, pyb, off);
                    pzb += __shfl_down_sync(0xffffffffu, pzb, off);
                }
                if (lane == 0) {
                    const float c0 = 0.009021097956087905f;   // 1/(sqrt(3)*64)
                    const float c1 = 0.011048543456039806f;   // 1/(sqrt(2)*64)
                    sm[OFF_TMP + 160*20 + ra] = p0a*c0;
                    sm[OFF_SP1 + ra*4 + 0] = pxa*c1;
                    sm[OFF_SP1 + ra*4 + 1] = pya*c1;
                    sm[OFF_SP1 + ra*4 + 2] = pza*c1;
                    sm[OFF_TMP + 160*20 + rb] = p0b*c0;
                    sm[OFF_SP1 + rb*4 + 0] = pxb*c1;
                    sm[OFF_SP1 + rb*4 + 1] = pyb*c1;
                    sm[OFF_SP1 + rb*4 + 2] = pzb*c1;
                }
            }
        } else {
            if (t < 16) {
                sm[OFF_TMP + 160*20 + t] = 0.f;
                sm[OFF_SP1 + t*4 + 0] = 0.f;
                sm[OFF_SP1 + t*4 + 1] = 0.f;
                sm[OFF_SP1 + t*4 + 2] = 0.f;
            }
        }
        __syncthreads();

        // ---- op5: s_tilde = [s_k|n_k|p0](161) @ Ws[k] + bs[k]  (2 cols x 4 rows, packed) ----
        {
            int c2 = (t & 127) * 2, h4 = t >> 7;     // 4 groups of 4 rows
            ull aA01 = 0, aA23 = 0, aB01 = 0, aB23 = 0;
            const float* W = Ws + k*161*256;
            #pragma unroll 4
            for (int i = 0; i < 161; ++i) {
                const float2 w = *reinterpret_cast<const float2*>(&W[i*256 + c2]);
                ull wx = pk2(w.x, w.x), wy = pk2(w.y, w.y);
                const ulonglong2 xv = *reinterpret_cast<const ulonglong2*>(&sm[OFF_TMP + i*20 + h4*4]);
                aA01 = ffma2(xv.x, wx, aA01);
                aA23 = ffma2(xv.y, wx, aA23);
                aB01 = ffma2(xv.x, wy, aB01);
                aB23 = ffma2(xv.y, wy, aB23);
            }
            const float2 bb = *reinterpret_cast<const float2*>(&bs[k*256 + c2]);
            float a0,a1,a2,a3, b0,b1,b2,b3;
            upk2(a0, a1, aA01); upk2(a2, a3, aA23);
            upk2(b0, b1, aB01); upk2(b2, b3, aB23);
            float2 o;
            o.x = a0 + bb.x; o.y = b0 + bb.y;
            *reinterpret_cast<float2*>(&sm[OFF_SCUR + (h4*4 + 0)*256 + c2]) = o;
            o.x = a1 + bb.x; o.y = b1 + bb.y;
            *reinterpret_cast<float2*>(&sm[OFF_SCUR + (h4*4 + 1)*256 + c2]) = o;
            o.x = a2 + bb.x; o.y = b2 + bb.y;
            *reinterpret_cast<float2*>(&sm[OFF_SCUR + (h4*4 + 2)*256 + c2]) = o;
            o.x = a3 + bb.x; o.y = b3 + bb.y;
            *reinterpret_cast<float2*>(&sm[OFF_SCUR + (h4*4 + 3)*256 + c2]) = o;
        }

        // ---- op6: v1o, v1e -> Vcur (row-major) ----
        {
            int j = t & 63, rg = t >> 6;
            ull a0 = 0, a1 = 0, a2 = 0;
            const float* W = Wv1o + k*64*64;
            #pragma unroll 4
            for (int i = 0; i < 64; ++i) {
                float w = __ldg(&W[i*64 + j]);
                ull ww = pk2(w, w);
                a0 = ffma2(*reinterpret_cast<const ull*>(&vkbuf[(i*3 + 0)*18 + rg*2]), ww, a0);
                a1 = ffma2(*reinterpret_cast<const ull*>(&vkbuf[(i*3 + 1)*18 + rg*2]), ww, a1);
                a2 = ffma2(*reinterpret_cast<const ull*>(&vkbuf[(i*3 + 2)*18 + rg*2]), ww, a2);
            }
            float we = __ldg(&Wv1e[k*64 + j]);
            float va0,vb0,va1,vb1,va2,vb2;
            upk2(va0, vb0, a0); upk2(va1, vb1, a1); upk2(va2, vb2, a2);
            int ra = rg*2, rb = rg*2 + 1;
            sm[OFF_VCUR + ra*384 + j*3 + 0] = va0*0.125f;
            sm[OFF_VCUR + ra*384 + j*3 + 1] = va1*0.125f;
            sm[OFF_VCUR + ra*384 + j*3 + 2] = va2*0.125f;
            sm[OFF_VCUR + rb*384 + j*3 + 0] = vb0*0.125f;
            sm[OFF_VCUR + rb*384 + j*3 + 1] = vb1*0.125f;
            sm[OFF_VCUR + rb*384 + j*3 + 2] = vb2*0.125f;
            sm[OFF_VCUR + ra*384 + 192 + j*3 + 0] = sm[OFF_SP1 + ra*4 + 0]*we;
            sm[OFF_VCUR + ra*384 + 192 + j*3 + 1] = sm[OFF_SP1 + ra*4 + 1]*we;
            sm[OFF_VCUR + ra*384 + 192 + j*3 + 2] = sm[OFF_SP1 + ra*4 + 2]*we;
            sm[OFF_VCUR + rb*384 + 192 + j*3 + 0] = sm[OFF_SP1 + rb*4 + 0]*we;
            sm[OFF_VCUR + rb*384 + 192 + j*3 + 1] = sm[OFF_SP1 + rb*4 + 1]*we;
            sm[OFF_VCUR + rb*384 + 192 + j*3 + 2] = sm[OFF_SP1 + rb*4 + 2]*we;
        }
        __syncthreads();

        // ---- layernorm (warp per row) w/ fused m-norms; writes HBUF (row-major) ----
        {
            int r = t >> 5, lane = t & 31;
            float s = 0.f, s2 = 0.f;
            #pragma unroll
            for (int c = lane; c < 384; c += 32) {
                float v;
                if (c < 256) v = sm[OFF_SCUR + r*256 + c];
                else {
                    int idx = c - 256;
                    float a = sm[OFF_VCUR + r*384 + idx*3];
                    float b = sm[OFF_VCUR + r*384 + idx*3 + 1];
                    float d = sm[OFF_VCUR + r*384 + idx*3 + 2];
                    v = sqrtf(a*a + b*b + d*d);
                    sm[OFF_MBUF + r*128 + idx] = v;
                }
                s += v; s2 += v*v;
            }
            #pragma unroll
            for (int off = 16; off > 0; off >>= 1) {
                s  += __shfl_xor_sync(0xffffffffu, s,  off);
                s2 += __shfl_xor_sync(0xffffffffu, s2, off);
            }
            float mu   = s  * (1.f/384.f);
            float var  = s2 * (1.f/384.f) - mu*mu;
            float rstd = rsqrtf(var + 1e-5f);
            #pragma unroll
            for (int c = lane; c < 384; c += 32) {
                float v = (c < 256) ? sm[OFF_SCUR + r*256 + c] : sm[OFF_MBUF + r*128 + c - 256];
                sm[OFF_HBUF + r*384 + c] = (v - mu)*rstd*sm[OFF_GB + c] + sm[OFF_GB + 384 + c];
            }
            if (lane == 0) sm[OFF_EV + r*4 + k] = 0.f;
        }
        // spill S,V (float4, all threads)
        for (int idx = t; idx < ROWS*160; idx += NTHR) {
            int r = idx / 160, q = idx - r*160;
            float4 v;
            if (q < 64) v = *reinterpret_cast<const float4*>(&sm[OFF_SCUR + r*256 + q*4]);
            else        v = *reinterpret_cast<const float4*>(&sm[OFF_VCUR + r*384 + (q - 64)*4]);
            *reinterpret_cast<float4*>(&g_SV[(size_t)(r0 + r)*2560 + (size_t)k*640 + q*4]) = v;
        }
        __syncthreads();

        // ---- MLP: all 512 threads, i split in halves, packed along i ----
        {
            int c = t & 63, g = (t >> 6) & 3, hh = t >> 8;
            ull acc[4] = {};
            const float* Wp = Wm1 + hh*192*64;
            const int ibase = hh*192;
            #pragma unroll 2
            for (int i = 0; i < 192; i += 4) {
                float w0 = __ldg(&Wp[(i+0)*64 + c]);
                float w1 = __ldg(&Wp[(i+1)*64 + c]);
                float w2 = __ldg(&Wp[(i+2)*64 + c]);
                float w3 = __ldg(&Wp[(i+3)*64 + c]);
                ull wp01 = pk2(w0, w1), wp23 = pk2(w2, w3);
                #pragma unroll
                for (int rr = 0; rr < 4; ++rr) {
                    const ulonglong2 hv = *reinterpret_cast<const ulonglong2*>(&sm[OFF_HBUF + (g*4 + rr)*384 + ibase + i]);
                    acc[rr] = ffma2(hv.x, wp01, acc[rr]);
                    acc[rr] = ffma2(hv.y, wp23, acc[rr]);
                }
            }
            float accs[4];
            #pragma unroll
            for (int rr = 0; rr < 4; ++rr) {
                float lo, hi; upk2(lo, hi, acc[rr]);
                accs[rr] = lo + hi;
            }
            if (hh == 1) {
                float4 p; p.x = accs[0]; p.y = accs[1]; p.z = accs[2]; p.w = accs[3];
                *reinterpret_cast<float4*>(&sm[OFF_MBUF + (t - 256)*4]) = p;
            }
            __syncthreads();
            if (hh == 0) {
                const float4 p = *reinterpret_cast<const float4*>(&sm[OFF_MBUF + t*4]);
                accs[0] += p.x; accs[1] += p.y; accs[2] += p.z; accs[3] += p.w;
                float wm2c = sm[OFF_WM2 + c];
                float b1c  = sm[OFF_BM1 + c];
                float ep[4];
                #pragma unroll
                for (int rr = 0; rr < 4; ++rr) {
                    float a = accs[rr] + b1c;
                    ep[rr] = a/(1.f + expf(-a)) * wm2c;
                }
                int lane = t & 31;
                #pragma unroll
                for (int off = 16; off > 0; off >>= 1)
                    #pragma unroll
                    for (int rr = 0; rr < 4; ++rr)
                        ep[rr] += __shfl_down_sync(0xffffffffu, ep[rr], off);
                if (lane == 0) {
                    #pragma unroll
                    for (int rr = 0; rr < 4; ++rr)
                        atomicAdd(&sm[OFF_EV + (g*4 + rr)*4 + k], ep[rr]);
                }
            }
        }

        { float* tp = vkbuf; vkbuf = vpbuf; vpbuf = tp; }
        __syncthreads();
    }

    // ---- softmax over K (bm2 cancels in softmax) ----
    if (t < ROWS) {
        float e0 = sm[OFF_EV + t*4 + 0], e1 = sm[OFF_EV + t*4 + 1];
        float e2 = sm[OFF_EV + t*4 + 2], e3 = sm[OFF_EV + t*4 + 3];
        float mx = fmaxf(fmaxf(e0, e1), fmaxf(e2, e3));
        float z0 = expf(e0 - mx), z1 = expf(e1 - mx), z2 = expf(e2 - mx), z3 = expf(e3 - mx);
        float inv = 1.f/(z0 + z1 + z2 + z3);
        g_alpha[(size_t)(r0 + t)*4 + 0] = z0*inv;
        g_alpha[(size_t)(r0 + t)*4 + 1] = z1*inv;
        g_alpha[(size_t)(r0 + t)*4 + 2] = z2*inv;
        g_alpha[(size_t)(r0 + t)*4 + 3] = z3*inv;
    }
}

// out = concat(flatten((alpha*S).sum(k)), flatten((alpha*V).sum(k)))
// 2 rows per 320-thread block; one float4 output per thread.
__global__ void fuse_k2(float* __restrict__ out)
{
    __shared__ float al[8];
    const int t  = threadIdx.x;              // 0..319
    const int rb = blockIdx.x * 2;
    if (t < 8) al[t] = g_alpha[(size_t)rb*4 + t];
    __syncthreads();
    const int half = (t >= 160) ? 1 : 0;
    const int q = t - half*160;
    const int r = rb + half;
    const float* sv = g_SV + (size_t)r*2560 + q*4;
    const float a0 = al[half*4 + 0], a1 = al[half*4 + 1];
    const float a2 = al[half*4 + 2], a3 = al[half*4 + 3];
    const float4 v0 = *reinterpret_cast<const float4*>(sv);
    const float4 v1 = *reinterpret_cast<const float4*>(sv + 640);
    const float4 v2 = *reinterpret_cast<const float4*>(sv + 1280);
    const float4 v3 = *reinterpret_cast<const float4*>(sv + 1920);
    float4 o;
    o.x = a0*v0.x + a1*v1.x + a2*v2.x + a3*v3.x;
    o.y = a0*v0.y + a1*v1.y + a2*v2.y + a3*v3.y;
    o.z = a0*v0.z + a1*v1.z + a2*v2.z + a3*v3.z;
    o.w = a0*v0.w + a1*v1.w + a2*v2.w + a3*v3.w;
    if (q < 64) *reinterpret_cast<float4*>(&out[(size_t)r*256 + q*4]) = o;
    else        *reinterpret_cast<float4*>(&out[(size_t)NTOK*256 + (size_t)r*384 + (q - 64)*4]) = o;
}

extern "C" void kernel_launch(void* const* d_in, const int* in_sizes, int n_in,
                              void* d_out, int out_size)
{
    (void)in_sizes; (void)n_in; (void)out_size;
    cudaFuncSetAttribute(fuse_k1, cudaFuncAttributeMaxDynamicSharedMemorySize, SMEM_BYTES);

    fuse_k1<<<NTOK/ROWS, NTHR, SMEM_BYTES>>>(
        (const float*)d_in[0],  (const float*)d_in[1],  (const float*)d_in[2],
        (const float*)d_in[3],  (const float*)d_in[4],  (const float*)d_in[5],
        (const float*)d_in[6],  (const float*)d_in[7],  (const float*)d_in[8],
        (const float*)d_in[9],  (const float*)d_in[10], (const float*)d_in[11],
        (const float*)d_in[12], (const float*)d_in[13], (const float*)d_in[14],
        (const float*)d_in[15], (const float*)d_in[16], (const float*)d_in[17],
        (const float*)d_in[18]);

    fuse_k2<<<NTOK/2, 320>>>((float*)d_out);
}

// round 9
// speedup vs baseline: 1.9580x; 1.3795x over previous
#include <cuda_runtime.h>
#include <math.h>

#define NTOK 80000
#define KK   4
#define ROWS 16
#define NTHR 512

typedef unsigned long long ull;

// ---------------- f32x2 packed helpers ----------------
__device__ __forceinline__ ull pk2(float lo, float hi) {
    ull r;
    asm("mov.b64 %0, {%1, %2};" : "=l"(r) : "r"(__float_as_uint(lo)), "r"(__float_as_uint(hi)));
    return r;
}
__device__ __forceinline__ void upk2(float& lo, float& hi, ull v) {
    unsigned int a, b;
    asm("mov.b64 {%0, %1}, %2;" : "=r"(a), "=r"(b) : "l"(v));
    lo = __uint_as_float(a); hi = __uint_as_float(b);
}
__device__ __forceinline__ ull ffma2(ull a, ull b, ull c) {
    ull d;
    asm("fma.rn.f32x2 %0, %1, %2, %3;" : "=l"(d) : "l"(a), "l"(b), "l"(c));
    return d;
}
__device__ __forceinline__ ull fmul2(ull a, ull b) {
    ull d;
    asm("mul.rn.f32x2 %0, %1, %2;" : "=l"(d) : "l"(a), "l"(b));
    return d;
}

// ---------------- smem layout (float offsets), ~109 KB -> 2 CTAs/SM ----------------
constexpr int OFF_SCUR = 0;                  // 16*256 = 4096 (U1_T scratch during op4)
constexpr int OFF_VCUR = OFF_SCUR + 4096;    // 16*384 = 6144 (U0_T scratch during op4)
constexpr int OFF_XS   = OFF_VCUR + 6144;    // transposed x, stride 20: 192*20 = 3840
constexpr int OFF_TMP  = OFF_XS   + 3840;    // transposed [s_k|n_k|p0], stride 20: 161*20 -> 3232
constexpr int OFF_VKA  = OFF_TMP  + 3232;    // transposed v_k, stride 18: 192*18 = 3456
constexpr int OFF_VKB  = OFF_VKA  + 3456;    // 3456
constexpr int OFF_MBUF = OFF_VKB  + 3456;    // 16*128 = 2048 (m-norms; MLP partial buf)
constexpr int OFF_GB   = OFF_MBUF + 2048;    // gamma 384 + beta 384
constexpr int OFF_BM1  = OFF_GB   + 768;     // 64
constexpr int OFF_WM2  = OFF_BM1  + 64;      // 64
constexpr int OFF_SP1  = OFF_WM2  + 64;      // 16*4
constexpr int OFF_EV   = OFF_SP1  + 64;      // 16*4 (e scores, then alpha)
constexpr int SMEM_FLOATS = OFF_EV + 64;     // 27296 floats
constexpr int SMEM_BYTES  = SMEM_FLOATS * 4; // 109184 B -> 2 blocks/SM
// hbuf (row-major LN output, 16*384=6144) overlays freed XS+TMP (7072)
constexpr int OFF_HBUF = OFF_XS;

// ---------------- global scratch (no allocs allowed) ----------------
__device__ __align__(16) float g_SV[(size_t)NTOK * 2560];  // [row][k][640] : S(256) then V(384)

__global__ void __launch_bounds__(NTHR, 2)
fuse_k1(const float* __restrict__ x0, const float* __restrict__ x1,
        const float* __restrict__ x2, const float* __restrict__ x3,
        const float* __restrict__ W_l0, const float* __restrict__ W_l1,
        const float* __restrict__ W_l2, const float* __restrict__ W_tp0,
        const float* __restrict__ W_tp1, const float* __restrict__ Ws,
        const float* __restrict__ bs, const float* __restrict__ Wv1o,
        const float* __restrict__ Wv1e, const float* __restrict__ gamma,
        const float* __restrict__ beta, const float* __restrict__ Wm1,
        const float* __restrict__ bm1, const float* __restrict__ Wm2,
        const float* __restrict__ bm2, float* __restrict__ out)
{
    extern __shared__ float sm[];
    const int t  = threadIdx.x;
    const int r0 = blockIdx.x * ROWS;

    // stage small block-resident constants
    for (int i = t; i < 384; i += NTHR) { sm[OFF_GB + i] = gamma[i]; sm[OFF_GB + 384 + i] = beta[i]; }
    if (t < 64) { sm[OFF_BM1 + t] = bm1[t]; sm[OFF_WM2 + t] = Wm2[t]; }
    __syncthreads();

    const float* xs_ptr[KK] = {x0, x1, x2, x3};
    float* vkbuf = sm + OFF_VKA;   // transposed [(j*3+m)*18 + r]
    float* vpbuf = sm + OFF_VKB;

    for (int k = 0; k < KK; ++k) {
        const float* xg = xs_ptr[k];

        // ---- stage x_s (transposed, stride 20) ----
        for (int idx = t; idx < ROWS*128; idx += NTHR) {
            int r = idx >> 7, c = idx & 127;
            sm[OFF_XS + c*20 + r] = xg[(size_t)(r0 + r)*480 + c];
        }
        __syncthreads();

        // ---- op1: s_k[j] = inv0 * sum_i x_s[i] W_l0[k][i][j]  (packed rows) ----
        {
            int j = t & 127, rq = t >> 7;            // 4 groups of 4 rows
            ull a01 = 0, a23 = 0;
            const float* W = W_l0 + k*128*128;
            #pragma unroll 8
            for (int i = 0; i < 128; ++i) {
                float w = __ldg(&W[i*128 + j]);
                ull ww = pk2(w, w);
                const ulonglong2 xv = *reinterpret_cast<const ulonglong2*>(&sm[OFF_XS + i*20 + rq*4]);
                a01 = ffma2(xv.x, ww, a01);
                a23 = ffma2(xv.y, ww, a23);
            }
            const ull ss = pk2(0.08838834764831845f, 0.08838834764831845f);  // 1/sqrt(128)
            *reinterpret_cast<ull*>(&sm[OFF_TMP + j*20 + rq*4    ]) = fmul2(a01, ss);
            *reinterpret_cast<ull*>(&sm[OFF_TMP + j*20 + rq*4 + 2]) = fmul2(a23, ss);
        }
        __syncthreads();

        // ---- stage x_v (192 cols) ----
        for (int idx = t; idx < ROWS*192; idx += NTHR) {
            int r = idx / 192, c = idx % 192;
            sm[OFF_XS + c*20 + r] = xg[(size_t)(r0 + r)*480 + 128 + c];
        }
        __syncthreads();

        // ---- op2: v_k (packed row pairs) -> vk_T stride 18 ----
        {
            int j = t & 63, rg = t >> 6;             // 8 groups of 2 rows
            ull a0 = 0, a1 = 0, a2 = 0;
            const float* W = W_l1 + k*64*64;
            #pragma unroll 8
            for (int i = 0; i < 64; ++i) {
                float w = __ldg(&W[i*64 + j]);
                ull ww = pk2(w, w);
                a0 = ffma2(*reinterpret_cast<const ull*>(&sm[OFF_XS + (i*3 + 0)*20 + rg*2]), ww, a0);
                a1 = ffma2(*reinterpret_cast<const ull*>(&sm[OFF_XS + (i*3 + 1)*20 + rg*2]), ww, a1);
                a2 = ffma2(*reinterpret_cast<const ull*>(&sm[OFF_XS + (i*3 + 2)*20 + rg*2]), ww, a2);
            }
            const ull ei = pk2(0.125f, 0.125f);
            *reinterpret_cast<ull*>(&vkbuf[(j*3 + 0)*18 + rg*2]) = fmul2(a0, ei);
            *reinterpret_cast<ull*>(&vkbuf[(j*3 + 1)*18 + rg*2]) = fmul2(a1, ei);
            *reinterpret_cast<ull*>(&vkbuf[(j*3 + 2)*18 + rg*2]) = fmul2(a2, ei);
        }
        __syncthreads();

        // ---- stage x_T (160 cols) ----
        for (int idx = t; idx < ROWS*160; idx += NTHR) {
            int r = idx / 160, c = idx % 160;
            sm[OFF_XS + c*20 + r] = xg[(size_t)(r0 + r)*480 + 320 + c];
        }
        __syncthreads();

        // ---- op3 (all threads): n_k into TMP ----
        {
            int j = t & 31, r = t >> 5;
            float a[5] = {};
            const float* W = W_l2 + k*32*32;
            #pragma unroll 8
            for (int i = 0; i < 32; ++i) {
                float w = __ldg(&W[i*32 + j]);
                #pragma unroll
                for (int m = 0; m < 5; ++m) a[m] += sm[OFF_XS + (i*5 + m)*20 + r]*w;
            }
            float s2 = a[0]*a[0] + a[1]*a[1] + a[2]*a[2] + a[3]*a[3] + a[4]*a[4];
            sm[OFF_TMP + (128 + j)*20 + r] = sqrtf(s2)*0.17677669529663687f;  // 1/sqrt(32)
        }

        // ---- op4-GEMM (all threads, packed): U0_T -> VCUR, U1_T -> SCUR ----
        if (k > 0) {
            int j = t & 63, rg = t >> 6;
            ull u0[3] = {}, u1[3] = {};
            #pragma unroll 4
            for (int i = 0; i < 64; ++i) {
                float w0 = __ldg(&W_tp0[i*64 + j]);
                float w1 = __ldg(&W_tp1[i*64 + j]);
                ull ww0 = pk2(w0, w0), ww1 = pk2(w1, w1);
                #pragma unroll
                for (int m = 0; m < 3; ++m) {
                    ull vp = *reinterpret_cast<const ull*>(&vkbuf[(i*3 + m)*18 + rg*2]);
                    u0[m] = ffma2(vp, ww0, u0[m]);
                    u1[m] = ffma2(vp, ww1, u1[m]);
                }
            }
            #pragma unroll
            for (int m = 0; m < 3; ++m) {
                *reinterpret_cast<ull*>(&sm[OFF_VCUR + (j*3 + m)*18 + rg*2]) = u0[m];
                *reinterpret_cast<ull*>(&sm[OFF_SCUR + (j*3 + m)*18 + rg*2]) = u1[m];
            }
        }
        __syncthreads();

        // ---- op4-reduce: p0/p1 per row (warps 0-7, 2 rows/warp) ----
        if (k > 0) {
            int w = t >> 5, lane = t & 31;
            if (w < 8) {
                int ra = 2*w, rb = 2*w + 1;
                float p0a=0,pxa=0,pya=0,pza=0, p0b=0,pxb=0,pyb=0,pzb=0;
                #pragma unroll
                for (int jj = 0; jj < 2; ++jj) {
                    int j = jj*32 + lane;
                    float u00 = sm[OFF_VCUR + (j*3+0)*18 + ra];
                    float u01 = sm[OFF_VCUR + (j*3+1)*18 + ra];
                    float u02 = sm[OFF_VCUR + (j*3+2)*18 + ra];
                    float u10 = sm[OFF_SCUR + (j*3+0)*18 + ra];
                    float u11 = sm[OFF_SCUR + (j*3+1)*18 + ra];
                    float u12 = sm[OFF_SCUR + (j*3+2)*18 + ra];
                    float vx = vpbuf[(j*3+0)*18 + ra];
                    float vy = vpbuf[(j*3+1)*18 + ra];
                    float vz = vpbuf[(j*3+2)*18 + ra];
                    p0a += u00*vx + u01*vy + u02*vz;
                    pxa += u11*vz - u12*vy;
                    pya += u12*vx - u10*vz;
                    pza += u10*vy - u11*vx;
                    u00 = sm[OFF_VCUR + (j*3+0)*18 + rb];
                    u01 = sm[OFF_VCUR + (j*3+1)*18 + rb];
                    u02 = sm[OFF_VCUR + (j*3+2)*18 + rb];
                    u10 = sm[OFF_SCUR + (j*3+0)*18 + rb];
                    u11 = sm[OFF_SCUR + (j*3+1)*18 + rb];
                    u12 = sm[OFF_SCUR + (j*3+2)*18 + rb];
                    vx = vpbuf[(j*3+0)*18 + rb];
                    vy = vpbuf[(j*3+1)*18 + rb];
                    vz = vpbuf[(j*3+2)*18 + rb];
                    p0b += u00*vx + u01*vy + u02*vz;
                    pxb += u11*vz - u12*vy;
                    pyb += u12*vx - u10*vz;
                    pzb += u10*vy - u11*vx;
                }
                #pragma unroll
                for (int off = 16; off > 0; off >>= 1) {
                    p0a += __shfl_down_sync(0xffffffffu, p0a, off);
                    pxa += __shfl_down_sync(0xffffffffu, pxa, off);
                    pya += __shfl_down_sync(0xffffffffu, pya, off);
                    pza += __shfl_down_sync(0xffffffffu, pza, off);
                    p0b += __shfl_down_sync(0xffffffffu, p0b, off);
                    pxb += __shfl_down_sync(0xffffffffu, pxb, off);
                    pyb += __shfl_down_sync(0xffffffffu, pyb, off);
                    pzb += __shfl_down_sync(0xffffffffu, pzb, off);
                }
                if (lane == 0) {
                    const float c0 = 0.009021097956087905f;   // 1/(sqrt(3)*64)
                    const float c1 = 0.011048543456039806f;   // 1/(sqrt(2)*64)
                    sm[OFF_TMP + 160*20 + ra] = p0a*c0;
                    sm[OFF_SP1 + ra*4 + 0] = pxa*c1;
                    sm[OFF_SP1 + ra*4 + 1] = pya*c1;
                    sm[OFF_SP1 + ra*4 + 2] = pza*c1;
                    sm[OFF_TMP + 160*20 + rb] = p0b*c0;
                    sm[OFF_SP1 + rb*4 + 0] = pxb*c1;
                    sm[OFF_SP1 + rb*4 + 1] = pyb*c1;
                    sm[OFF_SP1 + rb*4 + 2] = pzb*c1;
                }
            }
        } else {
            if (t < 16) {
                sm[OFF_TMP + 160*20 + t] = 0.f;
                sm[OFF_SP1 + t*4 + 0] = 0.f;
                sm[OFF_SP1 + t*4 + 1] = 0.f;
                sm[OFF_SP1 + t*4 + 2] = 0.f;
            }
        }
        __syncthreads();

        // ---- op5: s_tilde = [s_k|n_k|p0](161) @ Ws[k] + bs[k]  (2 cols x 4 rows, packed) ----
        {
            int c2 = (t & 127) * 2, h4 = t >> 7;     // 4 groups of 4 rows
            ull aA01 = 0, aA23 = 0, aB01 = 0, aB23 = 0;
            const float* W = Ws + k*161*256;
            #pragma unroll 8
            for (int i = 0; i < 160; ++i) {
                const float2 w = *reinterpret_cast<const float2*>(&W[i*256 + c2]);
                ull wx = pk2(w.x, w.x), wy = pk2(w.y, w.y);
                const ulonglong2 xv = *reinterpret_cast<const ulonglong2*>(&sm[OFF_TMP + i*20 + h4*4]);
                aA01 = ffma2(xv.x, wx, aA01);
                aA23 = ffma2(xv.y, wx, aA23);
                aB01 = ffma2(xv.x, wy, aB01);
                aB23 = ffma2(xv.y, wy, aB23);
            }
            {   // i = 160 (p0 column)
                const float2 w = *reinterpret_cast<const float2*>(&W[160*256 + c2]);
                ull wx = pk2(w.x, w.x), wy = pk2(w.y, w.y);
                const ulonglong2 xv = *reinterpret_cast<const ulonglong2*>(&sm[OFF_TMP + 160*20 + h4*4]);
                aA01 = ffma2(xv.x, wx, aA01);
                aA23 = ffma2(xv.y, wx, aA23);
                aB01 = ffma2(xv.x, wy, aB01);
                aB23 = ffma2(xv.y, wy, aB23);
            }
            const float2 bb = *reinterpret_cast<const float2*>(&bs[k*256 + c2]);
            float a0,a1,a2,a3, b0,b1,b2,b3;
            upk2(a0, a1, aA01); upk2(a2, a3, aA23);
            upk2(b0, b1, aB01); upk2(b2, b3, aB23);
            float2 o;
            o.x = a0 + bb.x; o.y = b0 + bb.y;
            *reinterpret_cast<float2*>(&sm[OFF_SCUR + (h4*4 + 0)*256 + c2]) = o;
            o.x = a1 + bb.x; o.y = b1 + bb.y;
            *reinterpret_cast<float2*>(&sm[OFF_SCUR + (h4*4 + 1)*256 + c2]) = o;
            o.x = a2 + bb.x; o.y = b2 + bb.y;
            *reinterpret_cast<float2*>(&sm[OFF_SCUR + (h4*4 + 2)*256 + c2]) = o;
            o.x = a3 + bb.x; o.y = b3 + bb.y;
            *reinterpret_cast<float2*>(&sm[OFF_SCUR + (h4*4 + 3)*256 + c2]) = o;
        }

        // ---- op6: v1o, v1e -> Vcur (row-major) ----
        {
            int j = t & 63, rg = t >> 6;
            ull a0 = 0, a1 = 0, a2 = 0;
            const float* W = Wv1o + k*64*64;
            #pragma unroll 8
            for (int i = 0; i < 64; ++i) {
                float w = __ldg(&W[i*64 + j]);
                ull ww = pk2(w, w);
                a0 = ffma2(*reinterpret_cast<const ull*>(&vkbuf[(i*3 + 0)*18 + rg*2]), ww, a0);
                a1 = ffma2(*reinterpret_cast<const ull*>(&vkbuf[(i*3 + 1)*18 + rg*2]), ww, a1);
                a2 = ffma2(*reinterpret_cast<const ull*>(&vkbuf[(i*3 + 2)*18 + rg*2]), ww, a2);
            }
            float we = __ldg(&Wv1e[k*64 + j]);
            float va0,vb0,va1,vb1,va2,vb2;
            upk2(va0, vb0, a0); upk2(va1, vb1, a1); upk2(va2, vb2, a2);
            int ra = rg*2, rb = rg*2 + 1;
            sm[OFF_VCUR + ra*384 + j*3 + 0] = va0*0.125f;
            sm[OFF_VCUR + ra*384 + j*3 + 1] = va1*0.125f;
            sm[OFF_VCUR + ra*384 + j*3 + 2] = va2*0.125f;
            sm[OFF_VCUR + rb*384 + j*3 + 0] = vb0*0.125f;
            sm[OFF_VCUR + rb*384 + j*3 + 1] = vb1*0.125f;
            sm[OFF_VCUR + rb*384 + j*3 + 2] = vb2*0.125f;
            sm[OFF_VCUR + ra*384 + 192 + j*3 + 0] = sm[OFF_SP1 + ra*4 + 0]*we;
            sm[OFF_VCUR + ra*384 + 192 + j*3 + 1] = sm[OFF_SP1 + ra*4 + 1]*we;
            sm[OFF_VCUR + ra*384 + 192 + j*3 + 2] = sm[OFF_SP1 + ra*4 + 2]*we;
            sm[OFF_VCUR + rb*384 + 192 + j*3 + 0] = sm[OFF_SP1 + rb*4 + 0]*we;
            sm[OFF_VCUR + rb*384 + 192 + j*3 + 1] = sm[OFF_SP1 + rb*4 + 1]*we;
            sm[OFF_VCUR + rb*384 + 192 + j*3 + 2] = sm[OFF_SP1 + rb*4 + 2]*we;
        }
        __syncthreads();

        // ---- layernorm (warp per row) w/ fused m-norms; writes HBUF (row-major) ----
        {
            int r = t >> 5, lane = t & 31;
            float s = 0.f, s2 = 0.f;
            #pragma unroll
            for (int c = lane; c < 384; c += 32) {
                float v;
                if (c < 256) v = sm[OFF_SCUR + r*256 + c];
                else {
                    int idx = c - 256;
                    float a = sm[OFF_VCUR + r*384 + idx*3];
                    float b = sm[OFF_VCUR + r*384 + idx*3 + 1];
                    float d = sm[OFF_VCUR + r*384 + idx*3 + 2];
                    v = sqrtf(a*a + b*b + d*d);
                    sm[OFF_MBUF + r*128 + idx] = v;
                }
                s += v; s2 += v*v;
            }
            #pragma unroll
            for (int off = 16; off > 0; off >>= 1) {
                s  += __shfl_xor_sync(0xffffffffu, s,  off);
                s2 += __shfl_xor_sync(0xffffffffu, s2, off);
            }
            float mu   = s  * (1.f/384.f);
            float var  = s2 * (1.f/384.f) - mu*mu;
            float rstd = rsqrtf(var + 1e-5f);
            #pragma unroll
            for (int c = lane; c < 384; c += 32) {
                float v = (c < 256) ? sm[OFF_SCUR + r*256 + c] : sm[OFF_MBUF + r*128 + c - 256];
                sm[OFF_HBUF + r*384 + c] = (v - mu)*rstd*sm[OFF_GB + c] + sm[OFF_GB + 384 + c];
            }
            if (lane == 0) sm[OFF_EV + r*4 + k] = 0.f;
        }
        // spill S,V (float4, all threads)
        for (int idx = t; idx < ROWS*160; idx += NTHR) {
            int r = idx / 160, q = idx - r*160;
            float4 v;
            if (q < 64) v = *reinterpret_cast<const float4*>(&sm[OFF_SCUR + r*256 + q*4]);
            else        v = *reinterpret_cast<const float4*>(&sm[OFF_VCUR + r*384 + (q - 64)*4]);
            *reinterpret_cast<float4*>(&g_SV[(size_t)(r0 + r)*2560 + (size_t)k*640 + q*4]) = v;
        }
        __syncthreads();

        // ---- MLP: all 512 threads, i split in halves, packed along i ----
        {
            int c = t & 63, g = (t >> 6) & 3, hh = t >> 8;
            ull acc[4] = {};
            const float* Wp = Wm1 + hh*192*64;
            const int ibase = hh*192;
            #pragma unroll 4
            for (int i = 0; i < 192; i += 4) {
                float w0 = __ldg(&Wp[(i+0)*64 + c]);
                float w1 = __ldg(&Wp[(i+1)*64 + c]);
                float w2 = __ldg(&Wp[(i+2)*64 + c]);
                float w3 = __ldg(&Wp[(i+3)*64 + c]);
                ull wp01 = pk2(w0, w1), wp23 = pk2(w2, w3);
                #pragma unroll
                for (int rr = 0; rr < 4; ++rr) {
                    const ulonglong2 hv = *reinterpret_cast<const ulonglong2*>(&sm[OFF_HBUF + (g*4 + rr)*384 + ibase + i]);
                    acc[rr] = ffma2(hv.x, wp01, acc[rr]);
                    acc[rr] = ffma2(hv.y, wp23, acc[rr]);
                }
            }
            float accs[4];
            #pragma unroll
            for (int rr = 0; rr < 4; ++rr) {
                float lo, hi; upk2(lo, hi, acc[rr]);
                accs[rr] = lo + hi;
            }
            if (hh == 1) {
                float4 p; p.x = accs[0]; p.y = accs[1]; p.z = accs[2]; p.w = accs[3];
                *reinterpret_cast<float4*>(&sm[OFF_MBUF + (t - 256)*4]) = p;
            }
            __syncthreads();
            if (hh == 0) {
                const float4 p = *reinterpret_cast<const float4*>(&sm[OFF_MBUF + t*4]);
                accs[0] += p.x; accs[1] += p.y; accs[2] += p.z; accs[3] += p.w;
                float wm2c = sm[OFF_WM2 + c];
                float b1c  = sm[OFF_BM1 + c];
                float ep[4];
                #pragma unroll
                for (int rr = 0; rr < 4; ++rr) {
                    float a = accs[rr] + b1c;
                    ep[rr] = a/(1.f + expf(-a)) * wm2c;
                }
                int lane = t & 31;
                #pragma unroll
                for (int off = 16; off > 0; off >>= 1)
                    #pragma unroll
                    for (int rr = 0; rr < 4; ++rr)
                        ep[rr] += __shfl_down_sync(0xffffffffu, ep[rr], off);
                if (lane == 0) {
                    #pragma unroll
                    for (int rr = 0; rr < 4; ++rr)
                        atomicAdd(&sm[OFF_EV + (g*4 + rr)*4 + k], ep[rr]);
                }
            }
        }

        { float* tp = vkbuf; vkbuf = vpbuf; vpbuf = tp; }
        __syncthreads();
    }

    // ---- softmax over K (bm2 cancels); alpha written in place into EV ----
    if (t < ROWS) {
        float e0 = sm[OFF_EV + t*4 + 0], e1 = sm[OFF_EV + t*4 + 1];
        float e2 = sm[OFF_EV + t*4 + 2], e3 = sm[OFF_EV + t*4 + 3];
        float mx = fmaxf(fmaxf(e0, e1), fmaxf(e2, e3));
        float z0 = expf(e0 - mx), z1 = expf(e1 - mx), z2 = expf(e2 - mx), z3 = expf(e3 - mx);
        float inv = 1.f/(z0 + z1 + z2 + z3);
        sm[OFF_EV + t*4 + 0] = z0*inv;
        sm[OFF_EV + t*4 + 1] = z1*inv;
        sm[OFF_EV + t*4 + 2] = z2*inv;
        sm[OFF_EV + t*4 + 3] = z3*inv;
    }
    __syncthreads();

    // ---- fused epilogue: out = sum_k alpha_k * SV_k  (g_SV is L2-hot, own block's data) ----
    for (int idx = t; idx < ROWS*160; idx += NTHR) {
        int r = idx / 160, q = idx - r*160;
        const float* sv = g_SV + (size_t)(r0 + r)*2560 + q*4;
        const float a0 = sm[OFF_EV + r*4 + 0], a1 = sm[OFF_EV + r*4 + 1];
        const float a2 = sm[OFF_EV + r*4 + 2], a3 = sm[OFF_EV + r*4 + 3];
        const float4 v0 = *reinterpret_cast<const float4*>(sv);
        const float4 v1 = *reinterpret_cast<const float4*>(sv + 640);
        const float4 v2 = *reinterpret_cast<const float4*>(sv + 1280);
        const float4 v3 = *reinterpret_cast<const float4*>(sv + 1920);
        float4 o;
        o.x = a0*v0.x + a1*v1.x + a2*v2.x + a3*v3.x;
        o.y = a0*v0.y + a1*v1.y + a2*v2.y + a3*v3.y;
        o.z = a0*v0.z + a1*v1.z + a2*v2.z + a3*v3.z;
        o.w = a0*v0.w + a1*v1.w + a2*v2.w + a3*v3.w;
        if (q < 64) *reinterpret_cast<float4*>(&out[(size_t)(r0 + r)*256 + q*4]) = o;
        else        *reinterpret_cast<float4*>(&out[(size_t)NTOK*256 + (size_t)(r0 + r)*384 + (q - 64)*4]) = o;
    }
}

extern "C" void kernel_launch(void* const* d_in, const int* in_sizes, int n_in,
                              void* d_out, int out_size)
{
    (void)in_sizes; (void)n_in; (void)out_size;
    cudaFuncSetAttribute(fuse_k1, cudaFuncAttributeMaxDynamicSharedMemorySize, SMEM_BYTES);

    fuse_k1<<<NTOK/ROWS, NTHR, SMEM_BYTES>>>(
        (const float*)d_in[0],  (const float*)d_in[1],  (const float*)d_in[2],
        (const float*)d_in[3],  (const float*)d_in[4],  (const float*)d_in[5],
        (const float*)d_in[6],  (const float*)d_in[7],  (const float*)d_in[8],
        (const float*)d_in[9],  (const float*)d_in[10], (const float*)d_in[11],
        (const float*)d_in[12], (const float*)d_in[13], (const float*)d_in[14],
        (const float*)d_in[15], (const float*)d_in[16], (const float*)d_in[17],
        (const float*)d_in[18], (float*)d_out);
}